// round 10
// baseline (speedup 1.0000x reference)
#include <cuda_runtime.h>
#include <cstdint>

#define BB 256
#define PP 196
#define DD 512
#define AA 512
#define MM (BB*PP)   // 50176

// ---------------- scratch (__device__ globals; no allocs) -------------------
__device__ float g_hidden[BB*AA];      // hidden + bv
__device__ float g_sh[BB*AA];          // st@Ws + bs + hidden (pre-tanh)
__device__ float g_z[BB*PP];           // logits
__device__ float g_sA[MM];             // per-row enc scale
__device__ float g_sB[AA];             // per-col Wv scale
// int8 planes, fragment-packed: [row][chunk c(16)][slot t(4)] uint2
// slot t of chunk c = { bytes4(k=32c+4t), bytes4(k=32c+16+4t) }
__device__ uint2 g_Ah[(size_t)MM*64];  // 25.7MB
__device__ uint2 g_Al[(size_t)MM*64];
__device__ uint2 g_Bh[AA*64];          // 256KB
__device__ uint2 g_Bl[AA*64];

// ---------------- helpers ---------------------------------------------------
__device__ __forceinline__ float tanhapx(float x) {
    float y; asm("tanh.approx.f32 %0, %1;" : "=f"(y) : "f"(x)); return y;
}
__device__ __forceinline__ void mmai(int* c, const uint32_t* a, const uint32_t* b) {
    asm volatile(
        "mma.sync.aligned.m16n8k32.row.col.s32.s8.s8.s32 "
        "{%0,%1,%2,%3}, {%4,%5,%6,%7}, {%8,%9}, {%0,%1,%2,%3};"
        : "+r"(c[0]), "+r"(c[1]), "+r"(c[2]), "+r"(c[3])
        : "r"(a[0]), "r"(a[1]), "r"(a[2]), "r"(a[3]), "r"(b[0]), "r"(b[1]));
}
__device__ __forceinline__ void cpasync16(uint32_t dst, const void* src) {
    asm volatile("cp.async.ca.shared.global [%0], [%1], 16;" :: "r"(dst), "l"(src));
}
#define CP_COMMIT() asm volatile("cp.async.commit_group;" ::: "memory")
#define CP_WAIT0()  asm volatile("cp.async.wait_group 0;" ::: "memory")

__device__ __forceinline__ uint32_t pack4(int b0, int b1, int b2, int b3) {
    return (uint32_t)(b0 & 255) | ((uint32_t)(b1 & 255) << 8) |
           ((uint32_t)(b2 & 255) << 16) | ((uint32_t)(b3 & 255) << 24);
}

// ---------------------------------------------------------------------------
// conv_enc: quantize enc rows to 15-bit split int8 planes + per-row scale.
// 16 rows/block, 16 threads/row (32 k each = one chunk).
// ---------------------------------------------------------------------------
__global__ void __launch_bounds__(256) conv_enc(const float* __restrict__ enc) {
    const int tid = threadIdx.x;
    const int row = blockIdx.x * 16 + (tid >> 4);
    const int sub = tid & 15;           // chunk index
    float v[32];
    const float4* src = (const float4*)&enc[(size_t)row*DD + sub*32];
    #pragma unroll
    for (int j = 0; j < 8; ++j) {
        const float4 f = src[j];
        v[j*4+0] = f.x; v[j*4+1] = f.y; v[j*4+2] = f.z; v[j*4+3] = f.w;
    }
    float mx = 0.f;
    #pragma unroll
    for (int j = 0; j < 32; ++j) mx = fmaxf(mx, fabsf(v[j]));
    #pragma unroll
    for (int off = 1; off < 16; off <<= 1)
        mx = fmaxf(mx, __shfl_xor_sync(0xffffffffu, mx, off));
    mx = fmaxf(mx, 1e-20f);
    const float inv = 16256.f / mx;
    if (sub == 0) g_sA[row] = mx / 16256.f;
    int ah[32], al[32];
    #pragma unroll
    for (int j = 0; j < 32; ++j) {
        const int A = __float2int_rn(v[j] * inv);
        const int h = (A + 64) >> 7;       // round(A/128)
        ah[j] = h;  al[j] = A - (h << 7);  // al in [-64,63]
    }
    const size_t base = (size_t)row*64 + sub*4;
    #pragma unroll
    for (int t = 0; t < 4; ++t) {
        g_Ah[base + t] = make_uint2(
            pack4(ah[4*t], ah[4*t+1], ah[4*t+2], ah[4*t+3]),
            pack4(ah[16+4*t], ah[16+4*t+1], ah[16+4*t+2], ah[16+4*t+3]));
        g_Al[base + t] = make_uint2(
            pack4(al[4*t], al[4*t+1], al[4*t+2], al[4*t+3]),
            pack4(al[16+4*t], al[16+4*t+1], al[16+4*t+2], al[16+4*t+3]));
    }
}

// ---------------------------------------------------------------------------
// conv_wvq: quantize Wv columns. 32 cols/block, 8 threads/col (64 k each).
// ---------------------------------------------------------------------------
__global__ void __launch_bounds__(256) conv_wvq(const float* __restrict__ Wv) {
    const int tid = threadIdx.x;
    const int n   = blockIdx.x * 32 + (tid >> 3);
    const int sub = tid & 7;            // covers chunks 2sub, 2sub+1
    float v[64];
    #pragma unroll 8
    for (int j = 0; j < 64; ++j)
        v[j] = Wv[(size_t)(sub*64 + j)*AA + n];
    float mx = 0.f;
    #pragma unroll
    for (int j = 0; j < 64; ++j) mx = fmaxf(mx, fabsf(v[j]));
    #pragma unroll
    for (int off = 1; off < 8; off <<= 1)
        mx = fmaxf(mx, __shfl_xor_sync(0xffffffffu, mx, off));
    mx = fmaxf(mx, 1e-20f);
    const float inv = 16256.f / mx;
    if (sub == 0) g_sB[n] = mx / 16256.f;
    int ah[64], al[64];
    #pragma unroll
    for (int j = 0; j < 64; ++j) {
        const int A = __float2int_rn(v[j] * inv);
        const int h = (A + 64) >> 7;
        ah[j] = h;  al[j] = A - (h << 7);
    }
    #pragma unroll
    for (int cc = 0; cc < 2; ++cc) {
        const int c = 2*sub + cc;
        const int o = cc*32;
        const size_t base = (size_t)n*64 + c*4;
        #pragma unroll
        for (int t = 0; t < 4; ++t) {
            g_Bh[base + t] = make_uint2(
                pack4(ah[o+4*t], ah[o+4*t+1], ah[o+4*t+2], ah[o+4*t+3]),
                pack4(ah[o+16+4*t], ah[o+16+4*t+1], ah[o+16+4*t+2], ah[o+16+4*t+3]));
            g_Bl[base + t] = make_uint2(
                pack4(al[o+4*t], al[o+4*t+1], al[o+4*t+2], al[o+4*t+3]),
                pack4(al[o+16+4*t], al[o+16+4*t+1], al[o+16+4*t+2], al[o+16+4*t+3]));
        }
    }
}

// ---------------------------------------------------------------------------
// K1: hidden = dh@Wh + bh (+bv stored);  g_sh = st@Ws + bs + hidden
// ---------------------------------------------------------------------------
__global__ void __launch_bounds__(256) k_prep(
    const float* __restrict__ dh, const float* __restrict__ st,
    const float* __restrict__ Wh, const float* __restrict__ bh,
    const float* __restrict__ Ws, const float* __restrict__ bs,
    const float* __restrict__ bv)
{
    __shared__ float dh_s[4][33], st_s[4][33];
    __shared__ float Wh_s[32][128], Ws_s[32][128];
    const int tid = threadIdx.x;
    const int b0  = blockIdx.y * 4;
    const int a0  = blockIdx.x * 128;
    const int al  = tid & 127;
    const int bl  = (tid >> 7) * 2;

    float acch[2] = {}, accs[2] = {};

    for (int kb = 0; kb < DD; kb += 32) {
        __syncthreads();
        if (tid < 128) {
            const int bb = tid >> 5, kk = tid & 31;
            dh_s[bb][kk] = dh[(b0 + bb)*DD + kb + kk];
            st_s[bb][kk] = st[(b0 + bb)*DD + kb + kk];
        }
        #pragma unroll
        for (int j = 0; j < 4; ++j) {
            const int i  = tid + j*256;
            const int kk = i >> 5, nq = i & 31;
            *(float4*)&Wh_s[kk][nq*4] = *(const float4*)&Wh[(size_t)(kb+kk)*AA + a0 + nq*4];
            *(float4*)&Ws_s[kk][nq*4] = *(const float4*)&Ws[(size_t)(kb+kk)*AA + a0 + nq*4];
        }
        __syncthreads();
        #pragma unroll 8
        for (int k = 0; k < 32; ++k) {
            const float wh = Wh_s[k][al], ws = Ws_s[k][al];
            #pragma unroll
            for (int bi = 0; bi < 2; ++bi) {
                acch[bi] += dh_s[bl+bi][k] * wh;
                accs[bi] += st_s[bl+bi][k] * ws;
            }
        }
    }
    #pragma unroll
    for (int bi = 0; bi < 2; ++bi) {
        const int b = b0 + bl + bi, a = a0 + al;
        const float h = acch[bi] + bh[a];
        g_hidden[(size_t)b*AA + a] = h + bv[a];
        g_sh[(size_t)b*AA + a]     = accs[bi] + bs[a] + h;
    }
}

// ---------------------------------------------------------------------------
// K2: int8 IMMA fused GEMM. BM=128, BN=128 (nt=4), BK=64 (2 k32 chunks/stage,
// 8 stages). 512 thr / 16 warps (4m x 4n), warp tile 32x32.
// All staging via cp.async (A and B pre-packed in global).
// v = sA[m]*sB[n]*(16384*acc1 + 128*acc2);  z += tanh(v + h)*Wav.
// ---------------------------------------------------------------------------
// per buffer: Ahi 0, Alo 8192, Bhi 16384, Blo 24576 ; chunk stride 4096,
// row stride 32B.
#define BUFSZ   32768
#define OFF_SAS 65536
#define OFF_H0  66048
#define OFF_H1  66560
#define OFF_WAV 67072
#define OFF_SB  67584
#define OFF_ZS  68096
#define K2_SMEM 68608

__global__ void __launch_bounds__(512, 1) k_zgemm(
    const float* __restrict__ Wav, const float* __restrict__ bav)
{
    extern __shared__ unsigned char sm[];
    float* sAs  = (float*)(sm + OFF_SAS);
    float* h0s  = (float*)(sm + OFF_H0);
    float* h1s  = (float*)(sm + OFF_H1);
    float* wavs = (float*)(sm + OFF_WAV);
    float* sBs  = (float*)(sm + OFF_SB);
    float* zs   = (float*)(sm + OFF_ZS);
    const uint32_t sbase = (uint32_t)__cvta_generic_to_shared(sm);

    const int tid  = threadIdx.x, lane = tid & 31, wid = tid >> 5;
    const int wm   = wid & 3;           // m-warp 0..3
    const int wn   = wid >> 2;          // n-warp 0..3
    const int gid  = lane >> 2, tig = lane & 3;
    const int m0   = blockIdx.x * 128;
    const int b0   = m0 / PP;
    const int b1   = (m0 + 127) / PP;
    const int bsplit = (b0 + 1) * PP;

    // cp.async slot decomposition: 2048 cp16/stage = 4/thread.
    // i = tid + j*512: region(2b: Ahi/Alo/Bhi/Blo), chunk cc, row, half.
    int rg_[4], cc_[4], rw_[4], hf_[4];
    #pragma unroll
    for (int j = 0; j < 4; ++j) {
        const int i = tid + j*512;
        rg_[j] = i >> 9;
        const int r = i & 511;
        cc_[j] = r >> 8;
        rw_[j] = (r & 255) >> 1;
        hf_[j] = r & 1;
    }

    if (tid < 128) { sAs[tid] = g_sA[m0 + tid]; zs[tid] = 0.f; }

    for (int nt = 0; nt < 4; ++nt) {
        const int n0 = nt * 128;
        __syncthreads();    // previous epilogue done; sAs/zs visible on nt=0
        if (tid < 128) {
            wavs[tid] = Wav[n0 + tid];
            h0s[tid]  = g_hidden[(size_t)b0*AA + n0 + tid];
            h1s[tid]  = g_hidden[(size_t)b1*AA + n0 + tid];
            sBs[tid]  = g_sB[n0 + tid];
        }

        int acc1[2][4][4], acc2[2][4][4];
        #pragma unroll
        for (int mi = 0; mi < 2; ++mi)
            #pragma unroll
            for (int ni = 0; ni < 4; ++ni)
                #pragma unroll
                for (int q = 0; q < 4; ++q) { acc1[mi][ni][q] = 0; acc2[mi][ni][q] = 0; }

        // ---- stage kc (chunk units) into buffer buf ----
        #define STAGE(kc, buf) do {                                          \
            _Pragma("unroll")                                                \
            for (int j = 0; j < 4; ++j) {                                    \
                const uint2* gsrc =                                          \
                    (rg_[j] == 0) ? g_Ah : (rg_[j] == 1) ? g_Al :            \
                    (rg_[j] == 2) ? g_Bh : g_Bl;                             \
                const int grow = ((rg_[j] < 2) ? m0 : n0) + rw_[j];          \
                const uint32_t dst = sbase + (uint32_t)(buf)*BUFSZ +         \
                    rg_[j]*8192u + cc_[j]*4096u + rw_[j]*32u + hf_[j]*16u;   \
                cpasync16(dst, &gsrc[(size_t)grow*64 +                       \
                                     ((kc) + cc_[j])*4 + hf_[j]*2]);         \
            }                                                                \
            CP_COMMIT();                                                     \
        } while (0)

        STAGE(0, 0);
        CP_WAIT0();
        __syncthreads();

        int cur = 0;
        #pragma unroll 1
        for (int s = 0; s < 8; ++s) {
            const int nxt = cur ^ 1;
            if (s < 7) STAGE(2*(s + 1), nxt);

            // ---- compute 2 chunks on buf[cur] ----
            #pragma unroll
            for (int cc = 0; cc < 2; ++cc) {
                const uint2* Ahi = (uint2*)(sm + cur*BUFSZ +         cc*4096);
                const uint2* Alo = (uint2*)(sm + cur*BUFSZ +  8192 + cc*4096);
                const uint2* Bhi = (uint2*)(sm + cur*BUFSZ + 16384 + cc*4096);
                const uint2* Blo = (uint2*)(sm + cur*BUFSZ + 24576 + cc*4096);
                uint32_t bh[4][2], bl[4][2];
                #pragma unroll
                for (int ni = 0; ni < 4; ++ni) {
                    const int nl = wn*32 + ni*8 + gid;
                    const uint2 ub = Bhi[nl*4 + tig];
                    const uint2 vb = Blo[nl*4 + tig];
                    bh[ni][0] = ub.x; bh[ni][1] = ub.y;
                    bl[ni][0] = vb.x; bl[ni][1] = vb.y;
                }
                #pragma unroll
                for (int mi = 0; mi < 2; ++mi) {
                    const int r = wm*32 + mi*16 + gid;
                    const uint2 u0 = Ahi[(r    )*4 + tig];
                    const uint2 u1 = Ahi[(r + 8)*4 + tig];
                    const uint2 v0 = Alo[(r    )*4 + tig];
                    const uint2 v1 = Alo[(r + 8)*4 + tig];
                    const uint32_t ah[4] = {u0.x, u1.x, u0.y, u1.y};
                    const uint32_t al[4] = {v0.x, v1.x, v0.y, v1.y};
                    #pragma unroll
                    for (int ni = 0; ni < 4; ++ni) {
                        mmai(acc1[mi][ni], ah, bh[ni]);
                        mmai(acc2[mi][ni], ah, bl[ni]);
                        mmai(acc2[mi][ni], al, bh[ni]);
                    }
                }
            }

            if (s < 7) CP_WAIT0();
            __syncthreads();
            cur = nxt;
        }

        // ---- epilogue ----
        float rs[2][2] = {0.f, 0.f, 0.f, 0.f};
        #pragma unroll
        for (int mi = 0; mi < 2; ++mi) {
            const int rl   = wm*32 + mi*16 + gid;
            const int r_lo = m0 + rl;
            const float sa0 = sAs[rl], sa1 = sAs[rl + 8];
            const float* hlo = (r_lo     >= bsplit) ? h1s : h0s;
            const float* hhi = (r_lo + 8 >= bsplit) ? h1s : h0s;
            #pragma unroll
            for (int ni = 0; ni < 4; ++ni) {
                const int c0 = wn*32 + ni*8 + 2*tig;
                const float w0 = wavs[c0], w1 = wavs[c0+1];
                const float sb0 = sBs[c0], sb1 = sBs[c0+1];
                const float v00 = sa0*sb0*(16384.f*(float)acc1[mi][ni][0] + 128.f*(float)acc2[mi][ni][0]);
                const float v01 = sa0*sb1*(16384.f*(float)acc1[mi][ni][1] + 128.f*(float)acc2[mi][ni][1]);
                const float v10 = sa1*sb0*(16384.f*(float)acc1[mi][ni][2] + 128.f*(float)acc2[mi][ni][2]);
                const float v11 = sa1*sb1*(16384.f*(float)acc1[mi][ni][3] + 128.f*(float)acc2[mi][ni][3]);
                rs[mi][0] += tanhapx(v00 + hlo[c0]) * w0 + tanhapx(v01 + hlo[c0+1]) * w1;
                rs[mi][1] += tanhapx(v10 + hhi[c0]) * w0 + tanhapx(v11 + hhi[c0+1]) * w1;
            }
        }
        #pragma unroll
        for (int off = 1; off <= 2; off <<= 1) {
            #pragma unroll
            for (int mi = 0; mi < 2; ++mi) {
                rs[mi][0] += __shfl_xor_sync(0xffffffffu, rs[mi][0], off);
                rs[mi][1] += __shfl_xor_sync(0xffffffffu, rs[mi][1], off);
            }
        }
        if (tig == 0) {
            #pragma unroll
            for (int mi = 0; mi < 2; ++mi) {
                atomicAdd(&zs[wm*32 + mi*16 + gid    ], rs[mi][0]);
                atomicAdd(&zs[wm*32 + mi*16 + gid + 8], rs[mi][1]);
            }
        }
        #undef STAGE
    }
    __syncthreads();
    if (tid < 128) g_z[m0 + tid] = zs[tid] + bav[0];
}

// ---------------------------------------------------------------------------
// K3: s_att reduce; softmax; beta; c_t; gated output
// ---------------------------------------------------------------------------
__global__ void __launch_bounds__(256) k_soft(
    const float* __restrict__ enc, const float* __restrict__ st,
    const float* __restrict__ Was, const float* __restrict__ bas,
    float* __restrict__ out)
{
    __shared__ float zsh[PP];
    __shared__ float alpha_sh[PP];
    __shared__ float red[256];
    const int tid = threadIdx.x;
    const int b   = blockIdx.x;
    const int y   = blockIdx.y;

    float sacc = 0.f;
    for (int i = tid; i < AA; i += 256)
        sacc += tanhapx(g_sh[(size_t)b*AA + i]) * Was[i];
    red[tid] = sacc;
    __syncthreads();
    for (int s = 128; s > 0; s >>= 1) {
        if (tid < s) red[tid] += red[tid + s];
        __syncthreads();
    }
    const float sa = red[0] + bas[0];
    __syncthreads();

    if (tid < PP) zsh[tid] = g_z[b*PP + tid];
    __syncthreads();

    red[tid] = (tid < PP) ? zsh[tid] : -1e30f;
    __syncthreads();
    for (int s = 128; s > 0; s >>= 1) {
        if (tid < s) red[tid] = fmaxf(red[tid], red[tid + s]);
        __syncthreads();
    }
    const float m1 = red[0];
    __syncthreads();

    const float e = (tid < PP) ? __expf(zsh[tid] - m1) : 0.f;
    red[tid] = e;
    __syncthreads();
    for (int s = 128; s > 0; s >>= 1) {
        if (tid < s) red[tid] += red[tid + s];
        __syncthreads();
    }
    const float sum1 = red[0];

    if (tid < PP) {
        const float alpha = e / sum1;
        alpha_sh[tid] = alpha;
        if (y == 0) out[BB*DD + b*PP + tid] = alpha;     // alpha_t
    }

    const float m2   = fmaxf(m1, sa);
    const float sum2 = sum1 * __expf(m1 - m2) + __expf(sa - m2);
    const float beta = __expf(sa - m2) / sum2;
    if (y == 0 && tid == 0) out[BB*DD + BB*PP + b] = beta;  // beta_t
    __syncthreads();

    const int d = y*256 + tid;
    const float* ep = enc + (size_t)b*PP*DD + d;
    float acc = 0.f;
    #pragma unroll 8
    for (int p = 0; p < PP; ++p)
        acc += ep[(size_t)p*DD] * alpha_sh[p];

    out[b*DD + d] = beta * st[b*DD + d] + (1.f - beta) * acc;  // c_hat_t
}

// ---------------------------------------------------------------------------
extern "C" void kernel_launch(void* const* d_in, const int* in_sizes, int n_in,
                              void* d_out, int out_size) {
    const float* enc = (const float*)d_in[0];
    const float* dh  = (const float*)d_in[1];
    const float* st  = (const float*)d_in[2];
    const float* Wv  = (const float*)d_in[3];
    const float* bv  = (const float*)d_in[4];
    const float* Wh  = (const float*)d_in[5];
    const float* bh  = (const float*)d_in[6];
    const float* Ws  = (const float*)d_in[7];
    const float* bs  = (const float*)d_in[8];
    const float* Wav = (const float*)d_in[9];
    const float* bav = (const float*)d_in[10];
    const float* Was = (const float*)d_in[11];
    const float* bas = (const float*)d_in[12];
    float* out = (float*)d_out;

    static int smem_set = 0;
    if (!smem_set) {
        cudaFuncSetAttribute(k_zgemm,
            cudaFuncAttributeMaxDynamicSharedMemorySize, K2_SMEM);
        smem_set = 1;
    }

    conv_enc<<<MM/16, 256>>>(enc);
    conv_wvq<<<16, 256>>>(Wv);
    k_prep  <<<dim3(4, 64), 256>>>(dh, st, Wh, bh, Ws, bs, bv);
    k_zgemm <<<MM/128, 512, K2_SMEM>>>(Wav, bav);
    k_soft  <<<dim3(BB, 2), 256>>>(enc, st, Was, bas, out);
}

// round 11
// speedup vs baseline: 2.5922x; 2.5922x over previous
#include <cuda_runtime.h>
#include <cuda_fp16.h>
#include <cstdint>

#define BB 256
#define PP 196
#define DD 512
#define AA 512
#define MM (BB*PP)   // 50176

// ---------------- scratch (__device__ globals; no allocs) -------------------
__device__ float g_hidden[BB*AA];      // hidden + bv
__device__ float g_sh[BB*AA];          // st@Ws + bs + hidden (pre-tanh)
__device__ float g_z[BB*PP];           // logits
// Wv^T fp16 plane, fragment-packed: [n(512)][chunk c(32)][slot t(4)] uint2
// slot t of chunk c = { f16pair(k=16c+2t), f16pair(k=16c+2t+8) }
__device__ uint4 g_WvH4[512*64];       // 512KB

// ---------------- helpers ---------------------------------------------------
__device__ __forceinline__ float tanhapx(float x) {
    float y; asm("tanh.approx.f32 %0, %1;" : "=f"(y) : "f"(x)); return y;
}
__device__ __forceinline__ uint32_t pack2h(float a, float b) {
    const __half ha = __float2half(a), hb = __float2half(b);
    return (uint32_t)__half_as_ushort(ha) |
           ((uint32_t)__half_as_ushort(hb) << 16);
}
// fp16 split: v = hi + lo to ~22 bits
__device__ __forceinline__ void split2h(float2 v, uint32_t& hi, uint32_t& lo) {
    const __half hx = __float2half(v.x), hy = __float2half(v.y);
    const float  rx = v.x - __half2float(hx), ry = v.y - __half2float(hy);
    hi = (uint32_t)__half_as_ushort(hx) | ((uint32_t)__half_as_ushort(hy) << 16);
    lo = pack2h(rx, ry);
}
__device__ __forceinline__ void mma16h(float* c, const uint32_t* a, const uint32_t* b) {
    asm volatile(
        "mma.sync.aligned.m16n8k16.row.col.f32.f16.f16.f32 "
        "{%0,%1,%2,%3}, {%4,%5,%6,%7}, {%8,%9}, {%0,%1,%2,%3};"
        : "+f"(c[0]), "+f"(c[1]), "+f"(c[2]), "+f"(c[3])
        : "r"(a[0]), "r"(a[1]), "r"(a[2]), "r"(a[3]), "r"(b[0]), "r"(b[1]));
}
__device__ __forceinline__ void cpasync16(uint32_t dst, const void* src) {
    asm volatile("cp.async.ca.shared.global [%0], [%1], 16;" :: "r"(dst), "l"(src));
}
#define CP_COMMIT() asm volatile("cp.async.commit_group;" ::: "memory")
#define CP_WAIT0()  asm volatile("cp.async.wait_group 0;" ::: "memory")

// ---------------------------------------------------------------------------
// conv_wv: Wv[k][n] fp32 -> g_WvH4 packed fp16 plane [n][k]
// ---------------------------------------------------------------------------
__global__ void __launch_bounds__(256) conv_wv(const float* __restrict__ Wv) {
    __shared__ float s[32][65];
    const int tid = threadIdx.x;
    const int n0  = blockIdx.x * 32;
    uint2* WvH2 = (uint2*)g_WvH4;

    for (int k0 = 0; k0 < DD; k0 += 64) {
        __syncthreads();
        #pragma unroll
        for (int j = 0; j < 8; ++j) {
            const int idx = tid + j*256;
            const int k = idx >> 5, n = idx & 31;
            s[n][k] = Wv[(size_t)(k0 + k)*AA + n0 + n];
        }
        __syncthreads();
        #pragma unroll
        for (int j = 0; j < 2; ++j) {
            const int i = tid + j*256;           // 32n x 16 slots
            const int n = i >> 4, q = i & 15;
            const int c = q >> 2, t = q & 3;
            const int kl = c*16 + 2*t;
            uint2 w;
            w.x = pack2h(s[n][kl],   s[n][kl+1]);
            w.y = pack2h(s[n][kl+8], s[n][kl+9]);
            WvH2[(size_t)(n0 + n)*128 + (k0/16 + c)*4 + t] = w;
        }
    }
}

// ---------------------------------------------------------------------------
// K1: hidden = dh@Wh + bh (+bv stored);  g_sh = st@Ws + bs + hidden
// ---------------------------------------------------------------------------
__global__ void __launch_bounds__(256) k_prep(
    const float* __restrict__ dh, const float* __restrict__ st,
    const float* __restrict__ Wh, const float* __restrict__ bh,
    const float* __restrict__ Ws, const float* __restrict__ bs,
    const float* __restrict__ bv)
{
    __shared__ float dh_s[4][33], st_s[4][33];
    __shared__ float Wh_s[32][128], Ws_s[32][128];
    const int tid = threadIdx.x;
    const int b0  = blockIdx.y * 4;
    const int a0  = blockIdx.x * 128;
    const int al  = tid & 127;
    const int bl  = (tid >> 7) * 2;

    float acch[2] = {}, accs[2] = {};

    for (int kb = 0; kb < DD; kb += 32) {
        __syncthreads();
        if (tid < 128) {
            const int bb = tid >> 5, kk = tid & 31;
            dh_s[bb][kk] = dh[(b0 + bb)*DD + kb + kk];
            st_s[bb][kk] = st[(b0 + bb)*DD + kb + kk];
        }
        #pragma unroll
        for (int j = 0; j < 4; ++j) {
            const int i  = tid + j*256;
            const int kk = i >> 5, nq = i & 31;
            *(float4*)&Wh_s[kk][nq*4] = *(const float4*)&Wh[(size_t)(kb+kk)*AA + a0 + nq*4];
            *(float4*)&Ws_s[kk][nq*4] = *(const float4*)&Ws[(size_t)(kb+kk)*AA + a0 + nq*4];
        }
        __syncthreads();
        #pragma unroll 8
        for (int k = 0; k < 32; ++k) {
            const float wh = Wh_s[k][al], ws = Ws_s[k][al];
            #pragma unroll
            for (int bi = 0; bi < 2; ++bi) {
                acch[bi] += dh_s[bl+bi][k] * wh;
                accs[bi] += st_s[bl+bi][k] * ws;
            }
        }
    }
    #pragma unroll
    for (int bi = 0; bi < 2; ++bi) {
        const int b = b0 + bl + bi, a = a0 + al;
        const float h = acch[bi] + bh[a];
        g_hidden[(size_t)b*AA + a] = h + bv[a];
        g_sh[(size_t)b*AA + a]     = accs[bi] + bs[a] + h;
    }
}

// ---------------------------------------------------------------------------
// K2: z[m] = bav + sum_a Wav[a]*tanh( enc[m,:]@Wv[:,a] + hidden[b(m),a] )
// fp16 m16n8k16, 2-pass split (A = ah + al fp16, B single fp16).
// BM=128, BN=256 (nt=2), BK=32; 512 thr / 16 warps (4m x 4n), warp 32x64.
// Double-buffered smem; per stage: cp.async B(next) + LDG A(next) ->
// compute(cur) -> STS A(next) -> cp.wait -> ONE sync.
// ---------------------------------------------------------------------------
#define ASTR 12              // uint2 per A row (8 used + 4 pad)
#define BSTR 12              // uint2 per B row
// per-buffer layout (bytes): Ah 0, Al 12288, Bh 24576; size 49152
#define BUFSZ   49152
#define OFF_H0  98304
#define OFF_H1  99328
#define OFF_WAV 100352
#define OFF_ZS  101376
#define K2_SMEM 101888

__global__ void __launch_bounds__(512, 1) k_zgemm(
    const float* __restrict__ enc, const float* __restrict__ Wav,
    const float* __restrict__ bav)
{
    extern __shared__ unsigned char sm[];
    float* h0s  = (float*)(sm + OFF_H0);
    float* h1s  = (float*)(sm + OFF_H1);
    float* wavs = (float*)(sm + OFF_WAV);
    float* zs   = (float*)(sm + OFF_ZS);
    const uint32_t sbase = (uint32_t)__cvta_generic_to_shared(sm);

    const int tid  = threadIdx.x, lane = tid & 31, wid = tid >> 5;
    const int wm   = wid & 3;           // m-warp 0..3
    const int wn   = wid >> 2;          // n-warp 0..3
    const int gid  = lane >> 2, tig = lane & 3;
    const int m0   = blockIdx.x * 128;
    const int b0   = m0 / PP;
    const int b1   = (m0 + 127) / PP;
    const int bsplit = (b0 + 1) * PP;

    // A staging slots (2 per thread): 128 rows x 8 q-slots
    int sr_[2], sq_[2], skl_[2];
    #pragma unroll
    for (int j = 0; j < 2; ++j) {
        const int slot = tid + j*512;
        sr_[j]  = slot >> 3;
        sq_[j]  = slot & 7;
        skl_[j] = ((sq_[j] >> 2) << 4) + ((sq_[j] & 3) << 1);   // 16c + 2t
    }
    // B staging slots (2 per thread): 256 n x 4 uint4 chunks
    int bn_[2], bs4_[2];
    #pragma unroll
    for (int j = 0; j < 2; ++j) {
        const int i = tid + j*512;
        bn_[j]  = i >> 2;
        bs4_[j] = i & 3;
    }

    if (tid < 128) zs[tid] = 0.f;

    for (int nt = 0; nt < 2; ++nt) {
        const int n0 = nt * 256;
        __syncthreads();   // previous epilogue done with smem
        for (int i = tid; i < 256; i += 512) {
            wavs[i] = Wav[n0 + i];
            h0s[i]  = g_hidden[(size_t)b0*AA + n0 + i];
            h1s[i]  = g_hidden[(size_t)b1*AA + n0 + i];
        }

        float acc[2][8][4];
        #pragma unroll
        for (int mi = 0; mi < 2; ++mi)
            #pragma unroll
            for (int ni = 0; ni < 8; ++ni)
                #pragma unroll
                for (int q = 0; q < 4; ++q) acc[mi][ni][q] = 0.f;

        // ---- prologue: stage kb=0 into buffer 0 ----
        {
            #pragma unroll
            for (int j = 0; j < 2; ++j) {
                const uint32_t dst = sbase + 24576u + bn_[j]*96u + bs4_[j]*16u;
                cpasync16(dst, &g_WvH4[(size_t)(n0 + bn_[j])*64 + bs4_[j]]);
            }
            CP_COMMIT();
            float2 pa[2][2];
            #pragma unroll
            for (int j = 0; j < 2; ++j) {
                const float* base = &enc[(size_t)(m0 + sr_[j])*DD + skl_[j]];
                pa[j][0] = *(const float2*)(base);
                pa[j][1] = *(const float2*)(base + 8);
            }
            uint2* Ah = (uint2*)(sm);
            uint2* Al = (uint2*)(sm + 12288);
            #pragma unroll
            for (int j = 0; j < 2; ++j) {
                uint32_t h0w, l0w, h1w, l1w;
                split2h(pa[j][0], h0w, l0w);
                split2h(pa[j][1], h1w, l1w);
                const int u = sr_[j]*ASTR + sq_[j];
                Ah[u] = make_uint2(h0w, h1w);
                Al[u] = make_uint2(l0w, l1w);
            }
            CP_WAIT0();
        }
        __syncthreads();

        int cur = 0;
        for (int kb = 0; kb < DD; kb += 32) {
            const int has_next = (kb + 32 < DD);
            const int nxt = cur ^ 1;
            float2 pa[2][2];
            if (has_next) {
                // B next stage: cp.async straight into buf[nxt] (no regs)
                const int kc = ((kb + 32) >> 4) * 2;
                #pragma unroll
                for (int j = 0; j < 2; ++j) {
                    const uint32_t dst = sbase + (uint32_t)nxt*BUFSZ +
                        24576u + bn_[j]*96u + bs4_[j]*16u;
                    cpasync16(dst, &g_WvH4[(size_t)(n0 + bn_[j])*64 + kc + bs4_[j]]);
                }
                CP_COMMIT();
                // A next stage: prefetch to regs (8 regs)
                #pragma unroll
                for (int j = 0; j < 2; ++j) {
                    const float* base =
                        &enc[(size_t)(m0 + sr_[j])*DD + kb + 32 + skl_[j]];
                    pa[j][0] = *(const float2*)(base);
                    pa[j][1] = *(const float2*)(base + 8);
                }
            }

            // ---- compute on buf[cur] ----
            {
                uint2* Ah = (uint2*)(sm + cur*BUFSZ);
                uint2* Al = (uint2*)(sm + cur*BUFSZ + 12288);
                uint2* Bh = (uint2*)(sm + cur*BUFSZ + 24576);
                #pragma unroll
                for (int c = 0; c < 2; ++c) {
                    uint32_t ah[2][4], alo[2][4];
                    #pragma unroll
                    for (int mi = 0; mi < 2; ++mi) {
                        const int r = wm*32 + mi*16 + gid;
                        const uint2 u0 = Ah[(r    )*ASTR + c*4 + tig];
                        const uint2 u1 = Ah[(r + 8)*ASTR + c*4 + tig];
                        ah[mi][0] = u0.x; ah[mi][1] = u1.x;
                        ah[mi][2] = u0.y; ah[mi][3] = u1.y;
                        const uint2 v0 = Al[(r    )*ASTR + c*4 + tig];
                        const uint2 v1 = Al[(r + 8)*ASTR + c*4 + tig];
                        alo[mi][0] = v0.x; alo[mi][1] = v1.x;
                        alo[mi][2] = v0.y; alo[mi][3] = v1.y;
                    }
                    #pragma unroll
                    for (int ni = 0; ni < 8; ++ni) {
                        const int n = wn*64 + ni*8 + gid;
                        const uint2 ubh = Bh[n*BSTR + c*4 + tig];
                        const uint32_t bhf[2] = {ubh.x, ubh.y};
                        #pragma unroll
                        for (int mi = 0; mi < 2; ++mi) {
                            mma16h(acc[mi][ni], ah[mi],  bhf);
                            mma16h(acc[mi][ni], alo[mi], bhf);
                        }
                    }
                }
            }

            // ---- store next A stage into buf[nxt]; wait for B cp.async ----
            if (has_next) {
                uint2* Ah = (uint2*)(sm + nxt*BUFSZ);
                uint2* Al = (uint2*)(sm + nxt*BUFSZ + 12288);
                #pragma unroll
                for (int j = 0; j < 2; ++j) {
                    uint32_t h0w, l0w, h1w, l1w;
                    split2h(pa[j][0], h0w, l0w);
                    split2h(pa[j][1], h1w, l1w);
                    const int u = sr_[j]*ASTR + sq_[j];
                    Ah[u] = make_uint2(h0w, h1w);
                    Al[u] = make_uint2(l0w, l1w);
                }
                CP_WAIT0();
            }
            __syncthreads();
            cur = nxt;
        }

        // ---- epilogue: tanh(v + hidden) * Wav, row partial sums ----
        float rs[2][2] = {0.f, 0.f, 0.f, 0.f};
        #pragma unroll
        for (int mi = 0; mi < 2; ++mi) {
            const int r_lo = m0 + wm*32 + mi*16 + gid;
            const float* hlo = (r_lo     >= bsplit) ? h1s : h0s;
            const float* hhi = (r_lo + 8 >= bsplit) ? h1s : h0s;
            #pragma unroll
            for (int ni = 0; ni < 8; ++ni) {
                const int c0 = wn*64 + ni*8 + 2*tig;
                const float w0 = wavs[c0], w1 = wavs[c0+1];
                rs[mi][0] += tanhapx(acc[mi][ni][0] + hlo[c0  ]) * w0
                           + tanhapx(acc[mi][ni][1] + hlo[c0+1]) * w1;
                rs[mi][1] += tanhapx(acc[mi][ni][2] + hhi[c0  ]) * w0
                           + tanhapx(acc[mi][ni][3] + hhi[c0+1]) * w1;
            }
        }
        #pragma unroll
        for (int off = 1; off <= 2; off <<= 1) {
            #pragma unroll
            for (int mi = 0; mi < 2; ++mi) {
                rs[mi][0] += __shfl_xor_sync(0xffffffffu, rs[mi][0], off);
                rs[mi][1] += __shfl_xor_sync(0xffffffffu, rs[mi][1], off);
            }
        }
        if (tig == 0) {
            #pragma unroll
            for (int mi = 0; mi < 2; ++mi) {
                atomicAdd(&zs[wm*32 + mi*16 + gid    ], rs[mi][0]);
                atomicAdd(&zs[wm*32 + mi*16 + gid + 8], rs[mi][1]);
            }
        }
    }
    __syncthreads();
    if (tid < 128) g_z[m0 + tid] = zs[tid] + bav[0];
}

// ---------------------------------------------------------------------------
// K3: s_att reduce; softmax; beta; c_t; gated output
// ---------------------------------------------------------------------------
__global__ void __launch_bounds__(256) k_soft(
    const float* __restrict__ enc, const float* __restrict__ st,
    const float* __restrict__ Was, const float* __restrict__ bas,
    float* __restrict__ out)
{
    __shared__ float zsh[PP];
    __shared__ float alpha_sh[PP];
    __shared__ float red[256];
    const int tid = threadIdx.x;
    const int b   = blockIdx.x;
    const int y   = blockIdx.y;

    float sacc = 0.f;
    for (int i = tid; i < AA; i += 256)
        sacc += tanhapx(g_sh[(size_t)b*AA + i]) * Was[i];
    red[tid] = sacc;
    __syncthreads();
    for (int s = 128; s > 0; s >>= 1) {
        if (tid < s) red[tid] += red[tid + s];
        __syncthreads();
    }
    const float sa = red[0] + bas[0];
    __syncthreads();

    if (tid < PP) zsh[tid] = g_z[b*PP + tid];
    __syncthreads();

    red[tid] = (tid < PP) ? zsh[tid] : -1e30f;
    __syncthreads();
    for (int s = 128; s > 0; s >>= 1) {
        if (tid < s) red[tid] = fmaxf(red[tid], red[tid + s]);
        __syncthreads();
    }
    const float m1 = red[0];
    __syncthreads();

    const float e = (tid < PP) ? __expf(zsh[tid] - m1) : 0.f;
    red[tid] = e;
    __syncthreads();
    for (int s = 128; s > 0; s >>= 1) {
        if (tid < s) red[tid] += red[tid + s];
        __syncthreads();
    }
    const float sum1 = red[0];

    if (tid < PP) {
        const float alpha = e / sum1;
        alpha_sh[tid] = alpha;
        if (y == 0) out[BB*DD + b*PP + tid] = alpha;     // alpha_t
    }

    const float m2   = fmaxf(m1, sa);
    const float sum2 = sum1 * __expf(m1 - m2) + __expf(sa - m2);
    const float beta = __expf(sa - m2) / sum2;
    if (y == 0 && tid == 0) out[BB*DD + BB*PP + b] = beta;  // beta_t
    __syncthreads();

    const int d = y*256 + tid;
    const float* ep = enc + (size_t)b*PP*DD + d;
    float acc = 0.f;
    #pragma unroll 8
    for (int p = 0; p < PP; ++p)
        acc += ep[(size_t)p*DD] * alpha_sh[p];

    out[b*DD + d] = beta * st[b*DD + d] + (1.f - beta) * acc;  // c_hat_t
}

// ---------------------------------------------------------------------------
extern "C" void kernel_launch(void* const* d_in, const int* in_sizes, int n_in,
                              void* d_out, int out_size) {
    const float* enc = (const float*)d_in[0];
    const float* dh  = (const float*)d_in[1];
    const float* st  = (const float*)d_in[2];
    const float* Wv  = (const float*)d_in[3];
    const float* bv  = (const float*)d_in[4];
    const float* Wh  = (const float*)d_in[5];
    const float* bh  = (const float*)d_in[6];
    const float* Ws  = (const float*)d_in[7];
    const float* bs  = (const float*)d_in[8];
    const float* Wav = (const float*)d_in[9];
    const float* bav = (const float*)d_in[10];
    const float* Was = (const float*)d_in[11];
    const float* bas = (const float*)d_in[12];
    float* out = (float*)d_out;

    static int smem_set = 0;
    if (!smem_set) {
        cudaFuncSetAttribute(k_zgemm,
            cudaFuncAttributeMaxDynamicSharedMemorySize, K2_SMEM);
        smem_set = 1;
    }

    conv_wv<<<16, 256>>>(Wv);
    k_prep <<<dim3(4, 64), 256>>>(dh, st, Wh, bh, Ws, bs, bv);
    k_zgemm<<<MM/128, 512, K2_SMEM>>>(enc, Wav, bav);
    k_soft <<<dim3(BB, 2), 256>>>(enc, st, Was, bas, out);
}

// round 12
// speedup vs baseline: 2.6237x; 1.0122x over previous
#include <cuda_runtime.h>
#include <cuda_fp16.h>
#include <cstdint>

#define BB 256
#define PP 196
#define DD 512
#define AA 512
#define MM (BB*PP)   // 50176

// ---------------- scratch (__device__ globals; no allocs) -------------------
__device__ float g_hidden[BB*AA];      // hidden + bv
__device__ float g_sh[BB*AA];          // st@Ws + bs + hidden (pre-tanh)
__device__ float g_z[BB*PP];           // logits
// Wv^T fp16 plane, fragment-packed: [n(512)][chunk c(32)][slot t(4)] uint2
// slot t of chunk c = { f16pair(k=16c+2t), f16pair(k=16c+2t+8) }
__device__ uint4 g_WvH4[512*64];       // 512KB

// ---------------- helpers ---------------------------------------------------
__device__ __forceinline__ float tanhapx(float x) {
    float y; asm("tanh.approx.f32 %0, %1;" : "=f"(y) : "f"(x)); return y;
}
__device__ __forceinline__ uint32_t pack2h(float a, float b) {
    const __half ha = __float2half(a), hb = __float2half(b);
    return (uint32_t)__half_as_ushort(ha) |
           ((uint32_t)__half_as_ushort(hb) << 16);
}
// fp16 split: v = hi + lo to ~22 bits
__device__ __forceinline__ void split2h(float2 v, uint32_t& hi, uint32_t& lo) {
    const __half hx = __float2half(v.x), hy = __float2half(v.y);
    const float  rx = v.x - __half2float(hx), ry = v.y - __half2float(hy);
    hi = (uint32_t)__half_as_ushort(hx) | ((uint32_t)__half_as_ushort(hy) << 16);
    lo = pack2h(rx, ry);
}
__device__ __forceinline__ void mma16h(float* c, const uint32_t* a, const uint32_t* b) {
    asm volatile(
        "mma.sync.aligned.m16n8k16.row.col.f32.f16.f16.f32 "
        "{%0,%1,%2,%3}, {%4,%5,%6,%7}, {%8,%9}, {%0,%1,%2,%3};"
        : "+f"(c[0]), "+f"(c[1]), "+f"(c[2]), "+f"(c[3])
        : "r"(a[0]), "r"(a[1]), "r"(a[2]), "r"(a[3]), "r"(b[0]), "r"(b[1]));
}
__device__ __forceinline__ void cpasync16(uint32_t dst, const void* src) {
    asm volatile("cp.async.ca.shared.global [%0], [%1], 16;" :: "r"(dst), "l"(src));
}
#define CP_COMMIT() asm volatile("cp.async.commit_group;" ::: "memory")
#define CP_WAIT0()  asm volatile("cp.async.wait_group 0;" ::: "memory")

// ---------------------------------------------------------------------------
// conv_wv: Wv[k][n] fp32 -> g_WvH4 packed fp16 plane [n][k]
// ---------------------------------------------------------------------------
__global__ void __launch_bounds__(256) conv_wv(const float* __restrict__ Wv) {
    __shared__ float s[32][65];
    const int tid = threadIdx.x;
    const int n0  = blockIdx.x * 32;
    uint2* WvH2 = (uint2*)g_WvH4;

    for (int k0 = 0; k0 < DD; k0 += 64) {
        __syncthreads();
        #pragma unroll
        for (int j = 0; j < 8; ++j) {
            const int idx = tid + j*256;
            const int k = idx >> 5, n = idx & 31;
            s[n][k] = Wv[(size_t)(k0 + k)*AA + n0 + n];
        }
        __syncthreads();
        #pragma unroll
        for (int j = 0; j < 2; ++j) {
            const int i = tid + j*256;           // 32n x 16 slots
            const int n = i >> 4, q = i & 15;
            const int c = q >> 2, t = q & 3;
            const int kl = c*16 + 2*t;
            uint2 w;
            w.x = pack2h(s[n][kl],   s[n][kl+1]);
            w.y = pack2h(s[n][kl+8], s[n][kl+9]);
            WvH2[(size_t)(n0 + n)*128 + (k0/16 + c)*4 + t] = w;
        }
    }
}

// ---------------------------------------------------------------------------
// K1: hidden = dh@Wh + bh (+bv stored);  g_sh = st@Ws + bs + hidden
// grid (4 a-tiles x 64 b-tiles); tile 4b x 128a; BK=32.
// Register double-buffer: store(cur) -> prefetch(next) -> compute(cur).
// ---------------------------------------------------------------------------
__global__ void __launch_bounds__(256) k_prep(
    const float* __restrict__ dh, const float* __restrict__ st,
    const float* __restrict__ Wh, const float* __restrict__ bh,
    const float* __restrict__ Ws, const float* __restrict__ bs,
    const float* __restrict__ bv)
{
    __shared__ float dh_s[4][33], st_s[4][33];
    __shared__ float Wh_s[32][128], Ws_s[32][128];
    const int tid = threadIdx.x;
    const int b0  = blockIdx.y * 4;
    const int a0  = blockIdx.x * 128;
    const int al  = tid & 127;
    const int bl  = (tid >> 7) * 2;

    float acch[2] = {}, accs[2] = {};

    float4 pwh[4], pws[4];
    float  pdh = 0.f, pst = 0.f;
    const int wkk = tid >> 5, wnq = tid & 31;   // W slot (with +j*8 rows)
    const int dbb = tid >> 5, dkk = tid & 31;   // dh/st slot (tid<128)

    // prefetch stage 0
    #pragma unroll
    for (int j = 0; j < 4; ++j) {
        pwh[j] = *(const float4*)&Wh[(size_t)(wkk + j*8)*AA + a0 + wnq*4];
        pws[j] = *(const float4*)&Ws[(size_t)(wkk + j*8)*AA + a0 + wnq*4];
    }
    if (tid < 128) {
        pdh = dh[(b0 + dbb)*DD + dkk];
        pst = st[(b0 + dbb)*DD + dkk];
    }

    for (int kb = 0; kb < DD; kb += 32) {
        __syncthreads();
        if (tid < 128) {
            dh_s[dbb][dkk] = pdh;
            st_s[dbb][dkk] = pst;
        }
        #pragma unroll
        for (int j = 0; j < 4; ++j) {
            *(float4*)&Wh_s[wkk + j*8][wnq*4] = pwh[j];
            *(float4*)&Ws_s[wkk + j*8][wnq*4] = pws[j];
        }
        __syncthreads();
        if (kb + 32 < DD) {
            #pragma unroll
            for (int j = 0; j < 4; ++j) {
                pwh[j] = *(const float4*)&Wh[(size_t)(kb + 32 + wkk + j*8)*AA + a0 + wnq*4];
                pws[j] = *(const float4*)&Ws[(size_t)(kb + 32 + wkk + j*8)*AA + a0 + wnq*4];
            }
            if (tid < 128) {
                pdh = dh[(b0 + dbb)*DD + kb + 32 + dkk];
                pst = st[(b0 + dbb)*DD + kb + 32 + dkk];
            }
        }
        #pragma unroll 8
        for (int k = 0; k < 32; ++k) {
            const float wh = Wh_s[k][al], ws = Ws_s[k][al];
            #pragma unroll
            for (int bi = 0; bi < 2; ++bi) {
                acch[bi] += dh_s[bl+bi][k] * wh;
                accs[bi] += st_s[bl+bi][k] * ws;
            }
        }
    }
    #pragma unroll
    for (int bi = 0; bi < 2; ++bi) {
        const int b = b0 + bl + bi, a = a0 + al;
        const float h = acch[bi] + bh[a];
        g_hidden[(size_t)b*AA + a] = h + bv[a];
        g_sh[(size_t)b*AA + a]     = accs[bi] + bs[a] + h;
    }
}

// ---------------------------------------------------------------------------
// K2: z[m] = bav + sum_a Wav[a]*tanh( enc[m,:]@Wv[:,a] + hidden[b(m),a] )
// fp16 m16n8k16, 2-pass split (A = ah + al fp16, B single fp16).
// BM=128, BN=256 (nt=2), BK=32; 512 thr / 16 warps (4m x 4n), warp 32x64.
// (UNCHANGED from round 11 — at mma.sync throughput ceiling.)
// ---------------------------------------------------------------------------
#define ASTR 12              // uint2 per A row (8 used + 4 pad)
#define BSTR 12              // uint2 per B row
#define BUFSZ   49152
#define OFF_H0  98304
#define OFF_H1  99328
#define OFF_WAV 100352
#define OFF_ZS  101376
#define K2_SMEM 101888

__global__ void __launch_bounds__(512, 1) k_zgemm(
    const float* __restrict__ enc, const float* __restrict__ Wav,
    const float* __restrict__ bav)
{
    extern __shared__ unsigned char sm[];
    float* h0s  = (float*)(sm + OFF_H0);
    float* h1s  = (float*)(sm + OFF_H1);
    float* wavs = (float*)(sm + OFF_WAV);
    float* zs   = (float*)(sm + OFF_ZS);
    const uint32_t sbase = (uint32_t)__cvta_generic_to_shared(sm);

    const int tid  = threadIdx.x, lane = tid & 31, wid = tid >> 5;
    const int wm   = wid & 3;
    const int wn   = wid >> 2;
    const int gid  = lane >> 2, tig = lane & 3;
    const int m0   = blockIdx.x * 128;
    const int b0   = m0 / PP;
    const int b1   = (m0 + 127) / PP;
    const int bsplit = (b0 + 1) * PP;

    int sr_[2], sq_[2], skl_[2];
    #pragma unroll
    for (int j = 0; j < 2; ++j) {
        const int slot = tid + j*512;
        sr_[j]  = slot >> 3;
        sq_[j]  = slot & 7;
        skl_[j] = ((sq_[j] >> 2) << 4) + ((sq_[j] & 3) << 1);
    }
    int bn_[2], bs4_[2];
    #pragma unroll
    for (int j = 0; j < 2; ++j) {
        const int i = tid + j*512;
        bn_[j]  = i >> 2;
        bs4_[j] = i & 3;
    }

    if (tid < 128) zs[tid] = 0.f;

    for (int nt = 0; nt < 2; ++nt) {
        const int n0 = nt * 256;
        __syncthreads();
        for (int i = tid; i < 256; i += 512) {
            wavs[i] = Wav[n0 + i];
            h0s[i]  = g_hidden[(size_t)b0*AA + n0 + i];
            h1s[i]  = g_hidden[(size_t)b1*AA + n0 + i];
        }

        float acc[2][8][4];
        #pragma unroll
        for (int mi = 0; mi < 2; ++mi)
            #pragma unroll
            for (int ni = 0; ni < 8; ++ni)
                #pragma unroll
                for (int q = 0; q < 4; ++q) acc[mi][ni][q] = 0.f;

        {
            #pragma unroll
            for (int j = 0; j < 2; ++j) {
                const uint32_t dst = sbase + 24576u + bn_[j]*96u + bs4_[j]*16u;
                cpasync16(dst, &g_WvH4[(size_t)(n0 + bn_[j])*64 + bs4_[j]]);
            }
            CP_COMMIT();
            float2 pa[2][2];
            #pragma unroll
            for (int j = 0; j < 2; ++j) {
                const float* base = &enc[(size_t)(m0 + sr_[j])*DD + skl_[j]];
                pa[j][0] = *(const float2*)(base);
                pa[j][1] = *(const float2*)(base + 8);
            }
            uint2* Ah = (uint2*)(sm);
            uint2* Al = (uint2*)(sm + 12288);
            #pragma unroll
            for (int j = 0; j < 2; ++j) {
                uint32_t h0w, l0w, h1w, l1w;
                split2h(pa[j][0], h0w, l0w);
                split2h(pa[j][1], h1w, l1w);
                const int u = sr_[j]*ASTR + sq_[j];
                Ah[u] = make_uint2(h0w, h1w);
                Al[u] = make_uint2(l0w, l1w);
            }
            CP_WAIT0();
        }
        __syncthreads();

        int cur = 0;
        for (int kb = 0; kb < DD; kb += 32) {
            const int has_next = (kb + 32 < DD);
            const int nxt = cur ^ 1;
            float2 pa[2][2];
            if (has_next) {
                const int kc = ((kb + 32) >> 4) * 2;
                #pragma unroll
                for (int j = 0; j < 2; ++j) {
                    const uint32_t dst = sbase + (uint32_t)nxt*BUFSZ +
                        24576u + bn_[j]*96u + bs4_[j]*16u;
                    cpasync16(dst, &g_WvH4[(size_t)(n0 + bn_[j])*64 + kc + bs4_[j]]);
                }
                CP_COMMIT();
                #pragma unroll
                for (int j = 0; j < 2; ++j) {
                    const float* base =
                        &enc[(size_t)(m0 + sr_[j])*DD + kb + 32 + skl_[j]];
                    pa[j][0] = *(const float2*)(base);
                    pa[j][1] = *(const float2*)(base + 8);
                }
            }

            {
                uint2* Ah = (uint2*)(sm + cur*BUFSZ);
                uint2* Al = (uint2*)(sm + cur*BUFSZ + 12288);
                uint2* Bh = (uint2*)(sm + cur*BUFSZ + 24576);
                #pragma unroll
                for (int c = 0; c < 2; ++c) {
                    uint32_t ah[2][4], alo[2][4];
                    #pragma unroll
                    for (int mi = 0; mi < 2; ++mi) {
                        const int r = wm*32 + mi*16 + gid;
                        const uint2 u0 = Ah[(r    )*ASTR + c*4 + tig];
                        const uint2 u1 = Ah[(r + 8)*ASTR + c*4 + tig];
                        ah[mi][0] = u0.x; ah[mi][1] = u1.x;
                        ah[mi][2] = u0.y; ah[mi][3] = u1.y;
                        const uint2 v0 = Al[(r    )*ASTR + c*4 + tig];
                        const uint2 v1 = Al[(r + 8)*ASTR + c*4 + tig];
                        alo[mi][0] = v0.x; alo[mi][1] = v1.x;
                        alo[mi][2] = v0.y; alo[mi][3] = v1.y;
                    }
                    #pragma unroll
                    for (int ni = 0; ni < 8; ++ni) {
                        const int n = wn*64 + ni*8 + gid;
                        const uint2 ubh = Bh[n*BSTR + c*4 + tig];
                        const uint32_t bhf[2] = {ubh.x, ubh.y};
                        #pragma unroll
                        for (int mi = 0; mi < 2; ++mi) {
                            mma16h(acc[mi][ni], ah[mi],  bhf);
                            mma16h(acc[mi][ni], alo[mi], bhf);
                        }
                    }
                }
            }

            if (has_next) {
                uint2* Ah = (uint2*)(sm + nxt*BUFSZ);
                uint2* Al = (uint2*)(sm + nxt*BUFSZ + 12288);
                #pragma unroll
                for (int j = 0; j < 2; ++j) {
                    uint32_t h0w, l0w, h1w, l1w;
                    split2h(pa[j][0], h0w, l0w);
                    split2h(pa[j][1], h1w, l1w);
                    const int u = sr_[j]*ASTR + sq_[j];
                    Ah[u] = make_uint2(h0w, h1w);
                    Al[u] = make_uint2(l0w, l1w);
                }
                CP_WAIT0();
            }
            __syncthreads();
            cur = nxt;
        }

        float rs[2][2] = {0.f, 0.f, 0.f, 0.f};
        #pragma unroll
        for (int mi = 0; mi < 2; ++mi) {
            const int r_lo = m0 + wm*32 + mi*16 + gid;
            const float* hlo = (r_lo     >= bsplit) ? h1s : h0s;
            const float* hhi = (r_lo + 8 >= bsplit) ? h1s : h0s;
            #pragma unroll
            for (int ni = 0; ni < 8; ++ni) {
                const int c0 = wn*64 + ni*8 + 2*tig;
                const float w0 = wavs[c0], w1 = wavs[c0+1];
                rs[mi][0] += tanhapx(acc[mi][ni][0] + hlo[c0  ]) * w0
                           + tanhapx(acc[mi][ni][1] + hlo[c0+1]) * w1;
                rs[mi][1] += tanhapx(acc[mi][ni][2] + hhi[c0  ]) * w0
                           + tanhapx(acc[mi][ni][3] + hhi[c0+1]) * w1;
            }
        }
        #pragma unroll
        for (int off = 1; off <= 2; off <<= 1) {
            #pragma unroll
            for (int mi = 0; mi < 2; ++mi) {
                rs[mi][0] += __shfl_xor_sync(0xffffffffu, rs[mi][0], off);
                rs[mi][1] += __shfl_xor_sync(0xffffffffu, rs[mi][1], off);
            }
        }
        if (tig == 0) {
            #pragma unroll
            for (int mi = 0; mi < 2; ++mi) {
                atomicAdd(&zs[wm*32 + mi*16 + gid    ], rs[mi][0]);
                atomicAdd(&zs[wm*32 + mi*16 + gid + 8], rs[mi][1]);
            }
        }
    }
    __syncthreads();
    if (tid < 128) g_z[m0 + tid] = zs[tid] + bav[0];
}

// ---------------------------------------------------------------------------
// K3: s_att reduce; softmax; beta; c_t; gated output
// grid (B, 4): each block owns 128 d's; c_t by 2 threads/d (98 p's each).
// ---------------------------------------------------------------------------
__global__ void __launch_bounds__(256) k_soft(
    const float* __restrict__ enc, const float* __restrict__ st,
    const float* __restrict__ Was, const float* __restrict__ bas,
    float* __restrict__ out)
{
    __shared__ float zsh[PP];
    __shared__ float alpha_sh[PP];
    __shared__ float red[256];
    const int tid = threadIdx.x;
    const int b   = blockIdx.x;
    const int y   = blockIdx.y;

    float sacc = 0.f;
    for (int i = tid; i < AA; i += 256)
        sacc += tanhapx(g_sh[(size_t)b*AA + i]) * Was[i];
    red[tid] = sacc;
    __syncthreads();
    for (int s = 128; s > 0; s >>= 1) {
        if (tid < s) red[tid] += red[tid + s];
        __syncthreads();
    }
    const float sa = red[0] + bas[0];
    __syncthreads();

    if (tid < PP) zsh[tid] = g_z[b*PP + tid];
    __syncthreads();

    red[tid] = (tid < PP) ? zsh[tid] : -1e30f;
    __syncthreads();
    for (int s = 128; s > 0; s >>= 1) {
        if (tid < s) red[tid] = fmaxf(red[tid], red[tid + s]);
        __syncthreads();
    }
    const float m1 = red[0];
    __syncthreads();

    const float e = (tid < PP) ? __expf(zsh[tid] - m1) : 0.f;
    red[tid] = e;
    __syncthreads();
    for (int s = 128; s > 0; s >>= 1) {
        if (tid < s) red[tid] += red[tid + s];
        __syncthreads();
    }
    const float sum1 = red[0];

    if (tid < PP) {
        const float alpha = e / sum1;
        alpha_sh[tid] = alpha;
        if (y == 0) out[BB*DD + b*PP + tid] = alpha;     // alpha_t
    }

    const float m2   = fmaxf(m1, sa);
    const float sum2 = sum1 * __expf(m1 - m2) + __expf(sa - m2);
    const float beta = __expf(sa - m2) / sum2;
    if (y == 0 && tid == 0) out[BB*DD + BB*PP + b] = beta;  // beta_t
    __syncthreads();

    // c_t: 2 threads per d, each half covers 98 p's
    const int t2   = tid >> 1;
    const int half = tid & 1;
    const int d    = y*128 + t2;
    const int p0   = half * 98;
    const float* ep = enc + (size_t)b*PP*DD + (size_t)p0*DD + d;
    float acc = 0.f;
    #pragma unroll 7
    for (int p = 0; p < 98; ++p)
        acc += ep[(size_t)p*DD] * alpha_sh[p0 + p];
    acc += __shfl_xor_sync(0xffffffffu, acc, 1);
    if (half == 0)
        out[b*DD + d] = beta * st[b*DD + d] + (1.f - beta) * acc;  // c_hat_t
}

// ---------------------------------------------------------------------------
extern "C" void kernel_launch(void* const* d_in, const int* in_sizes, int n_in,
                              void* d_out, int out_size) {
    const float* enc = (const float*)d_in[0];
    const float* dh  = (const float*)d_in[1];
    const float* st  = (const float*)d_in[2];
    const float* Wv  = (const float*)d_in[3];
    const float* bv  = (const float*)d_in[4];
    const float* Wh  = (const float*)d_in[5];
    const float* bh  = (const float*)d_in[6];
    const float* Ws  = (const float*)d_in[7];
    const float* bs  = (const float*)d_in[8];
    const float* Wav = (const float*)d_in[9];
    const float* bav = (const float*)d_in[10];
    const float* Was = (const float*)d_in[11];
    const float* bas = (const float*)d_in[12];
    float* out = (float*)d_out;

    static int smem_set = 0;
    if (!smem_set) {
        cudaFuncSetAttribute(k_zgemm,
            cudaFuncAttributeMaxDynamicSharedMemorySize, K2_SMEM);
        smem_set = 1;
    }

    conv_wv<<<16, 256>>>(Wv);
    k_prep <<<dim3(4, 64), 256>>>(dh, st, Wh, bh, Ws, bs, bv);
    k_zgemm<<<MM/128, 512, K2_SMEM>>>(enc, Wav, bav);
    k_soft <<<dim3(BB, 4), 256>>>(enc, st, Was, bas, out);
}

// round 13
// speedup vs baseline: 2.7627x; 1.0530x over previous
#include <cuda_runtime.h>
#include <cuda_fp16.h>
#include <cstdint>

#define BB 256
#define PP 196
#define DD 512
#define AA 512
#define MM (BB*PP)   // 50176

// ---------------- scratch (__device__ globals; no allocs) -------------------
__device__ float g_hidden[BB*AA];      // hidden + bv
__device__ float g_sh[BB*AA];          // st@Ws + bs + hidden (pre-tanh)
__device__ float g_z[BB*PP];           // logits
// Wv^T fp16 plane, fragment-packed: [n(512)][chunk c(32)][slot t(4)] uint2
// slot t of chunk c = { f16pair(k=16c+2t), f16pair(k=16c+2t+8) }
__device__ uint4 g_WvH4[512*64];       // 512KB

// ---------------- helpers ---------------------------------------------------
__device__ __forceinline__ float tanhapx(float x) {
    float y; asm("tanh.approx.f32 %0, %1;" : "=f"(y) : "f"(x)); return y;
}
__device__ __forceinline__ uint32_t pack2h(float a, float b) {
    const __half ha = __float2half(a), hb = __float2half(b);
    return (uint32_t)__half_as_ushort(ha) |
           ((uint32_t)__half_as_ushort(hb) << 16);
}
// fp16 split: v = hi + lo to ~22 bits
__device__ __forceinline__ void split2h(float2 v, uint32_t& hi, uint32_t& lo) {
    const __half hx = __float2half(v.x), hy = __float2half(v.y);
    const float  rx = v.x - __half2float(hx), ry = v.y - __half2float(hy);
    hi = (uint32_t)__half_as_ushort(hx) | ((uint32_t)__half_as_ushort(hy) << 16);
    lo = pack2h(rx, ry);
}
__device__ __forceinline__ void mma16h(float* c, const uint32_t* a, const uint32_t* b) {
    asm volatile(
        "mma.sync.aligned.m16n8k16.row.col.f32.f16.f16.f32 "
        "{%0,%1,%2,%3}, {%4,%5,%6,%7}, {%8,%9}, {%0,%1,%2,%3};"
        : "+f"(c[0]), "+f"(c[1]), "+f"(c[2]), "+f"(c[3])
        : "r"(a[0]), "r"(a[1]), "r"(a[2]), "r"(a[3]), "r"(b[0]), "r"(b[1]));
}
__device__ __forceinline__ void cpasync16(uint32_t dst, const void* src) {
    asm volatile("cp.async.ca.shared.global [%0], [%1], 16;" :: "r"(dst), "l"(src));
}
#define CP_COMMIT() asm volatile("cp.async.commit_group;" ::: "memory")
#define CP_WAIT0()  asm volatile("cp.async.wait_group 0;" ::: "memory")

// ---------------------------------------------------------------------------
// conv_wv: Wv[k][n] fp32 -> g_WvH4 packed fp16 plane [n][k]
// ---------------------------------------------------------------------------
__global__ void __launch_bounds__(256) conv_wv(const float* __restrict__ Wv) {
    __shared__ float s[32][65];
    const int tid = threadIdx.x;
    const int n0  = blockIdx.x * 32;
    uint2* WvH2 = (uint2*)g_WvH4;

    for (int k0 = 0; k0 < DD; k0 += 64) {
        __syncthreads();
        #pragma unroll
        for (int j = 0; j < 8; ++j) {
            const int idx = tid + j*256;
            const int k = idx >> 5, n = idx & 31;
            s[n][k] = Wv[(size_t)(k0 + k)*AA + n0 + n];
        }
        __syncthreads();
        #pragma unroll
        for (int j = 0; j < 2; ++j) {
            const int i = tid + j*256;           // 32n x 16 slots
            const int n = i >> 4, q = i & 15;
            const int c = q >> 2, t = q & 3;
            const int kl = c*16 + 2*t;
            uint2 w;
            w.x = pack2h(s[n][kl],   s[n][kl+1]);
            w.y = pack2h(s[n][kl+8], s[n][kl+9]);
            WvH2[(size_t)(n0 + n)*128 + (k0/16 + c)*4 + t] = w;
        }
    }
}

// ---------------------------------------------------------------------------
// K1: hidden = dh@Wh + bh (+bv stored);  g_sh = st@Ws + bs + hidden
// grid (4 a-tiles x 32 b-tiles) = 128 blocks; tile 8b x 128a; BK=32.
// Register double-buffer: store(cur) -> prefetch(next) -> compute(cur).
// ---------------------------------------------------------------------------
__global__ void __launch_bounds__(256) k_prep(
    const float* __restrict__ dh, const float* __restrict__ st,
    const float* __restrict__ Wh, const float* __restrict__ bh,
    const float* __restrict__ Ws, const float* __restrict__ bs,
    const float* __restrict__ bv)
{
    __shared__ float dh_s[8][33], st_s[8][33];
    __shared__ float Wh_s[32][128], Ws_s[32][128];
    const int tid = threadIdx.x;
    const int b0  = blockIdx.y * 8;
    const int a0  = blockIdx.x * 128;
    const int al  = tid & 127;
    const int bl  = (tid >> 7) * 4;      // batches bl..bl+3

    float acch[4] = {}, accs[4] = {};

    float4 pwh[4], pws[4];
    float  pdh, pst;
    const int wkk = tid >> 5, wnq = tid & 31;   // W slot (+j*8 rows)
    const int dbb = tid >> 5, dkk = tid & 31;   // dh/st slot (8x32 = all 256)

    // prefetch stage 0
    #pragma unroll
    for (int j = 0; j < 4; ++j) {
        pwh[j] = *(const float4*)&Wh[(size_t)(wkk + j*8)*AA + a0 + wnq*4];
        pws[j] = *(const float4*)&Ws[(size_t)(wkk + j*8)*AA + a0 + wnq*4];
    }
    pdh = dh[(b0 + dbb)*DD + dkk];
    pst = st[(b0 + dbb)*DD + dkk];

    for (int kb = 0; kb < DD; kb += 32) {
        __syncthreads();
        dh_s[dbb][dkk] = pdh;
        st_s[dbb][dkk] = pst;
        #pragma unroll
        for (int j = 0; j < 4; ++j) {
            *(float4*)&Wh_s[wkk + j*8][wnq*4] = pwh[j];
            *(float4*)&Ws_s[wkk + j*8][wnq*4] = pws[j];
        }
        __syncthreads();
        if (kb + 32 < DD) {
            #pragma unroll
            for (int j = 0; j < 4; ++j) {
                pwh[j] = *(const float4*)&Wh[(size_t)(kb + 32 + wkk + j*8)*AA + a0 + wnq*4];
                pws[j] = *(const float4*)&Ws[(size_t)(kb + 32 + wkk + j*8)*AA + a0 + wnq*4];
            }
            pdh = dh[(b0 + dbb)*DD + kb + 32 + dkk];
            pst = st[(b0 + dbb)*DD + kb + 32 + dkk];
        }
        #pragma unroll 4
        for (int k = 0; k < 32; ++k) {
            const float wh = Wh_s[k][al], ws = Ws_s[k][al];
            #pragma unroll
            for (int bi = 0; bi < 4; ++bi) {
                acch[bi] += dh_s[bl+bi][k] * wh;
                accs[bi] += st_s[bl+bi][k] * ws;
            }
        }
    }
    #pragma unroll
    for (int bi = 0; bi < 4; ++bi) {
        const int b = b0 + bl + bi, a = a0 + al;
        const float h = acch[bi] + bh[a];
        g_hidden[(size_t)b*AA + a] = h + bv[a];
        g_sh[(size_t)b*AA + a]     = accs[bi] + bs[a] + h;
    }
}

// ---------------------------------------------------------------------------
// K2: z[m] = bav + sum_a Wav[a]*tanh( enc[m,:]@Wv[:,a] + hidden[b(m),a] )
// fp16 m16n8k16, 2-pass split (A = ah + al fp16, B single fp16).
// BM=128, BN=256 (nt=2), BK=32; 512 thr / 16 warps (4m x 4n), warp 32x64.
// (UNCHANGED — at mma.sync throughput ceiling.)
// ---------------------------------------------------------------------------
#define ASTR 12              // uint2 per A row (8 used + 4 pad)
#define BSTR 12              // uint2 per B row
#define BUFSZ   49152
#define OFF_H0  98304
#define OFF_H1  99328
#define OFF_WAV 100352
#define OFF_ZS  101376
#define K2_SMEM 101888

__global__ void __launch_bounds__(512, 1) k_zgemm(
    const float* __restrict__ enc, const float* __restrict__ Wav,
    const float* __restrict__ bav)
{
    extern __shared__ unsigned char sm[];
    float* h0s  = (float*)(sm + OFF_H0);
    float* h1s  = (float*)(sm + OFF_H1);
    float* wavs = (float*)(sm + OFF_WAV);
    float* zs   = (float*)(sm + OFF_ZS);
    const uint32_t sbase = (uint32_t)__cvta_generic_to_shared(sm);

    const int tid  = threadIdx.x, lane = tid & 31, wid = tid >> 5;
    const int wm   = wid & 3;
    const int wn   = wid >> 2;
    const int gid  = lane >> 2, tig = lane & 3;
    const int m0   = blockIdx.x * 128;
    const int b0   = m0 / PP;
    const int b1   = (m0 + 127) / PP;
    const int bsplit = (b0 + 1) * PP;

    int sr_[2], sq_[2], skl_[2];
    #pragma unroll
    for (int j = 0; j < 2; ++j) {
        const int slot = tid + j*512;
        sr_[j]  = slot >> 3;
        sq_[j]  = slot & 7;
        skl_[j] = ((sq_[j] >> 2) << 4) + ((sq_[j] & 3) << 1);
    }
    int bn_[2], bs4_[2];
    #pragma unroll
    for (int j = 0; j < 2; ++j) {
        const int i = tid + j*512;
        bn_[j]  = i >> 2;
        bs4_[j] = i & 3;
    }

    if (tid < 128) zs[tid] = 0.f;

    for (int nt = 0; nt < 2; ++nt) {
        const int n0 = nt * 256;
        __syncthreads();
        for (int i = tid; i < 256; i += 512) {
            wavs[i] = Wav[n0 + i];
            h0s[i]  = g_hidden[(size_t)b0*AA + n0 + i];
            h1s[i]  = g_hidden[(size_t)b1*AA + n0 + i];
        }

        float acc[2][8][4];
        #pragma unroll
        for (int mi = 0; mi < 2; ++mi)
            #pragma unroll
            for (int ni = 0; ni < 8; ++ni)
                #pragma unroll
                for (int q = 0; q < 4; ++q) acc[mi][ni][q] = 0.f;

        {
            #pragma unroll
            for (int j = 0; j < 2; ++j) {
                const uint32_t dst = sbase + 24576u + bn_[j]*96u + bs4_[j]*16u;
                cpasync16(dst, &g_WvH4[(size_t)(n0 + bn_[j])*64 + bs4_[j]]);
            }
            CP_COMMIT();
            float2 pa[2][2];
            #pragma unroll
            for (int j = 0; j < 2; ++j) {
                const float* base = &enc[(size_t)(m0 + sr_[j])*DD + skl_[j]];
                pa[j][0] = *(const float2*)(base);
                pa[j][1] = *(const float2*)(base + 8);
            }
            uint2* Ah = (uint2*)(sm);
            uint2* Al = (uint2*)(sm + 12288);
            #pragma unroll
            for (int j = 0; j < 2; ++j) {
                uint32_t h0w, l0w, h1w, l1w;
                split2h(pa[j][0], h0w, l0w);
                split2h(pa[j][1], h1w, l1w);
                const int u = sr_[j]*ASTR + sq_[j];
                Ah[u] = make_uint2(h0w, h1w);
                Al[u] = make_uint2(l0w, l1w);
            }
            CP_WAIT0();
        }
        __syncthreads();

        int cur = 0;
        for (int kb = 0; kb < DD; kb += 32) {
            const int has_next = (kb + 32 < DD);
            const int nxt = cur ^ 1;
            float2 pa[2][2];
            if (has_next) {
                const int kc = ((kb + 32) >> 4) * 2;
                #pragma unroll
                for (int j = 0; j < 2; ++j) {
                    const uint32_t dst = sbase + (uint32_t)nxt*BUFSZ +
                        24576u + bn_[j]*96u + bs4_[j]*16u;
                    cpasync16(dst, &g_WvH4[(size_t)(n0 + bn_[j])*64 + kc + bs4_[j]]);
                }
                CP_COMMIT();
                #pragma unroll
                for (int j = 0; j < 2; ++j) {
                    const float* base =
                        &enc[(size_t)(m0 + sr_[j])*DD + kb + 32 + skl_[j]];
                    pa[j][0] = *(const float2*)(base);
                    pa[j][1] = *(const float2*)(base + 8);
                }
            }

            {
                uint2* Ah = (uint2*)(sm + cur*BUFSZ);
                uint2* Al = (uint2*)(sm + cur*BUFSZ + 12288);
                uint2* Bh = (uint2*)(sm + cur*BUFSZ + 24576);
                #pragma unroll
                for (int c = 0; c < 2; ++c) {
                    uint32_t ah[2][4], alo[2][4];
                    #pragma unroll
                    for (int mi = 0; mi < 2; ++mi) {
                        const int r = wm*32 + mi*16 + gid;
                        const uint2 u0 = Ah[(r    )*ASTR + c*4 + tig];
                        const uint2 u1 = Ah[(r + 8)*ASTR + c*4 + tig];
                        ah[mi][0] = u0.x; ah[mi][1] = u1.x;
                        ah[mi][2] = u0.y; ah[mi][3] = u1.y;
                        const uint2 v0 = Al[(r    )*ASTR + c*4 + tig];
                        const uint2 v1 = Al[(r + 8)*ASTR + c*4 + tig];
                        alo[mi][0] = v0.x; alo[mi][1] = v1.x;
                        alo[mi][2] = v0.y; alo[mi][3] = v1.y;
                    }
                    #pragma unroll
                    for (int ni = 0; ni < 8; ++ni) {
                        const int n = wn*64 + ni*8 + gid;
                        const uint2 ubh = Bh[n*BSTR + c*4 + tig];
                        const uint32_t bhf[2] = {ubh.x, ubh.y};
                        #pragma unroll
                        for (int mi = 0; mi < 2; ++mi) {
                            mma16h(acc[mi][ni], ah[mi],  bhf);
                            mma16h(acc[mi][ni], alo[mi], bhf);
                        }
                    }
                }
            }

            if (has_next) {
                uint2* Ah = (uint2*)(sm + nxt*BUFSZ);
                uint2* Al = (uint2*)(sm + nxt*BUFSZ + 12288);
                #pragma unroll
                for (int j = 0; j < 2; ++j) {
                    uint32_t h0w, l0w, h1w, l1w;
                    split2h(pa[j][0], h0w, l0w);
                    split2h(pa[j][1], h1w, l1w);
                    const int u = sr_[j]*ASTR + sq_[j];
                    Ah[u] = make_uint2(h0w, h1w);
                    Al[u] = make_uint2(l0w, l1w);
                }
                CP_WAIT0();
            }
            __syncthreads();
            cur = nxt;
        }

        float rs[2][2] = {0.f, 0.f, 0.f, 0.f};
        #pragma unroll
        for (int mi = 0; mi < 2; ++mi) {
            const int r_lo = m0 + wm*32 + mi*16 + gid;
            const float* hlo = (r_lo     >= bsplit) ? h1s : h0s;
            const float* hhi = (r_lo + 8 >= bsplit) ? h1s : h0s;
            #pragma unroll
            for (int ni = 0; ni < 8; ++ni) {
                const int c0 = wn*64 + ni*8 + 2*tig;
                const float w0 = wavs[c0], w1 = wavs[c0+1];
                rs[mi][0] += tanhapx(acc[mi][ni][0] + hlo[c0  ]) * w0
                           + tanhapx(acc[mi][ni][1] + hlo[c0+1]) * w1;
                rs[mi][1] += tanhapx(acc[mi][ni][2] + hhi[c0  ]) * w0
                           + tanhapx(acc[mi][ni][3] + hhi[c0+1]) * w1;
            }
        }
        #pragma unroll
        for (int off = 1; off <= 2; off <<= 1) {
            #pragma unroll
            for (int mi = 0; mi < 2; ++mi) {
                rs[mi][0] += __shfl_xor_sync(0xffffffffu, rs[mi][0], off);
                rs[mi][1] += __shfl_xor_sync(0xffffffffu, rs[mi][1], off);
            }
        }
        if (tig == 0) {
            #pragma unroll
            for (int mi = 0; mi < 2; ++mi) {
                atomicAdd(&zs[wm*32 + mi*16 + gid    ], rs[mi][0]);
                atomicAdd(&zs[wm*32 + mi*16 + gid + 8], rs[mi][1]);
            }
        }
    }
    __syncthreads();
    if (tid < 128) g_z[m0 + tid] = zs[tid] + bav[0];
}

// ---------------------------------------------------------------------------
// K3: s_att reduce; softmax; beta; c_t; gated output
// grid (B, 4): 128 d's/block. c_t: 32 d-quads x 8 p-groups, float4-coalesced,
// smem tree-reduce over p-groups.
// ---------------------------------------------------------------------------
__global__ void __launch_bounds__(256) k_soft(
    const float* __restrict__ enc, const float* __restrict__ st,
    const float* __restrict__ Was, const float* __restrict__ bas,
    float* __restrict__ out)
{
    __shared__ float zsh[PP];
    __shared__ float alpha_sh[PP];
    __shared__ float red[256];
    __shared__ float4 red4[8][32];
    const int tid = threadIdx.x;
    const int b   = blockIdx.x;
    const int y   = blockIdx.y;

    float sacc = 0.f;
    for (int i = tid; i < AA; i += 256)
        sacc += tanhapx(g_sh[(size_t)b*AA + i]) * Was[i];
    red[tid] = sacc;
    __syncthreads();
    for (int s = 128; s > 0; s >>= 1) {
        if (tid < s) red[tid] += red[tid + s];
        __syncthreads();
    }
    const float sa = red[0] + bas[0];
    __syncthreads();

    if (tid < PP) zsh[tid] = g_z[b*PP + tid];
    __syncthreads();

    red[tid] = (tid < PP) ? zsh[tid] : -1e30f;
    __syncthreads();
    for (int s = 128; s > 0; s >>= 1) {
        if (tid < s) red[tid] = fmaxf(red[tid], red[tid + s]);
        __syncthreads();
    }
    const float m1 = red[0];
    __syncthreads();

    const float e = (tid < PP) ? __expf(zsh[tid] - m1) : 0.f;
    red[tid] = e;
    __syncthreads();
    for (int s = 128; s > 0; s >>= 1) {
        if (tid < s) red[tid] += red[tid + s];
        __syncthreads();
    }
    const float sum1 = red[0];

    if (tid < PP) {
        const float alpha = e / sum1;
        alpha_sh[tid] = alpha;
        if (y == 0) out[BB*DD + b*PP + tid] = alpha;     // alpha_t
    }

    const float m2   = fmaxf(m1, sa);
    const float sum2 = sum1 * __expf(m1 - m2) + __expf(sa - m2);
    const float beta = __expf(sa - m2) / sum2;
    if (y == 0 && tid == 0) out[BB*DD + BB*PP + b] = beta;  // beta_t
    __syncthreads();

    // c_t: 32 d-quads x 8 p-groups; warp = one p-group, fully coalesced.
    const int q  = tid & 31;          // d-quad within block's 128 d's
    const int g  = tid >> 5;          // p-group
    const int d4 = y*128 + q*4;
    const float* eb = enc + (size_t)b*PP*DD + d4;
    float4 a4 = make_float4(0.f, 0.f, 0.f, 0.f);
    for (int p = g; p < PP; p += 8) {
        const float4 ev = *(const float4*)(eb + (size_t)p*DD);
        const float al = alpha_sh[p];
        a4.x += ev.x*al; a4.y += ev.y*al; a4.z += ev.z*al; a4.w += ev.w*al;
    }
    red4[g][q] = a4;
    __syncthreads();
    #pragma unroll
    for (int s = 4; s > 0; s >>= 1) {
        if (g < s) {
            float4 o = red4[g + s][q];
            a4.x += o.x; a4.y += o.y; a4.z += o.z; a4.w += o.w;
            red4[g][q] = a4;
        }
        __syncthreads();
    }
    if (g == 0) {
        const float4 s4 = *(const float4*)&st[b*DD + d4];
        float4 o;
        o.x = beta*s4.x + (1.f - beta)*a4.x;
        o.y = beta*s4.y + (1.f - beta)*a4.y;
        o.z = beta*s4.z + (1.f - beta)*a4.z;
        o.w = beta*s4.w + (1.f - beta)*a4.w;
        *(float4*)&out[b*DD + d4] = o;                   // c_hat_t
    }
}

// ---------------------------------------------------------------------------
extern "C" void kernel_launch(void* const* d_in, const int* in_sizes, int n_in,
                              void* d_out, int out_size) {
    const float* enc = (const float*)d_in[0];
    const float* dh  = (const float*)d_in[1];
    const float* st  = (const float*)d_in[2];
    const float* Wv  = (const float*)d_in[3];
    const float* bv  = (const float*)d_in[4];
    const float* Wh  = (const float*)d_in[5];
    const float* bh  = (const float*)d_in[6];
    const float* Ws  = (const float*)d_in[7];
    const float* bs  = (const float*)d_in[8];
    const float* Wav = (const float*)d_in[9];
    const float* bav = (const float*)d_in[10];
    const float* Was = (const float*)d_in[11];
    const float* bas = (const float*)d_in[12];
    float* out = (float*)d_out;

    static int smem_set = 0;
    if (!smem_set) {
        cudaFuncSetAttribute(k_zgemm,
            cudaFuncAttributeMaxDynamicSharedMemorySize, K2_SMEM);
        smem_set = 1;
    }

    conv_wv<<<16, 256>>>(Wv);
    k_prep <<<dim3(4, 32), 256>>>(dh, st, Wh, bh, Ws, bs, bv);
    k_zgemm<<<MM/128, 512, K2_SMEM>>>(enc, Wav, bav);
    k_soft <<<dim3(BB, 4), 256>>>(enc, st, Was, bas, out);
}

// round 14
// speedup vs baseline: 3.9598x; 1.4333x over previous
#include <cuda_runtime.h>
#include <cuda_fp16.h>
#include <cstdint>

#define BB 256
#define PP 196
#define DD 512
#define AA 512
#define MM (BB*PP)   // 50176

// ---------------- scratch (__device__ globals; no allocs) -------------------
__device__ float g_hidden[BB*AA];      // hidden + bv
__device__ float g_sh[BB*AA];          // st@Ws + bs + hidden (pre-tanh)
__device__ float g_z[BB*PP];           // logits
// Wv^T fp16 plane, fragment-packed: [n(512)][chunk c(32)][slot t(4)] uint2
// slot t of chunk c = { f16pair(k=16c+2t), f16pair(k=16c+2t+8) }
__device__ uint4 g_WvH4[512*64];       // 512KB

// ---------------- helpers ---------------------------------------------------
__device__ __forceinline__ float tanhapx(float x) {
    float y; asm("tanh.approx.f32 %0, %1;" : "=f"(y) : "f"(x)); return y;
}
__device__ __forceinline__ uint32_t pack2h(float a, float b) {
    const __half ha = __float2half(a), hb = __float2half(b);
    return (uint32_t)__half_as_ushort(ha) |
           ((uint32_t)__half_as_ushort(hb) << 16);
}
__device__ __forceinline__ void mma16h(float* c, const uint32_t* a, const uint32_t* b) {
    asm volatile(
        "mma.sync.aligned.m16n8k16.row.col.f32.f16.f16.f32 "
        "{%0,%1,%2,%3}, {%4,%5,%6,%7}, {%8,%9}, {%0,%1,%2,%3};"
        : "+f"(c[0]), "+f"(c[1]), "+f"(c[2]), "+f"(c[3])
        : "r"(a[0]), "r"(a[1]), "r"(a[2]), "r"(a[3]), "r"(b[0]), "r"(b[1]));
}
__device__ __forceinline__ void cpasync16(uint32_t dst, const void* src) {
    asm volatile("cp.async.ca.shared.global [%0], [%1], 16;" :: "r"(dst), "l"(src));
}
#define CP_COMMIT() asm volatile("cp.async.commit_group;" ::: "memory")
#define CP_WAIT0()  asm volatile("cp.async.wait_group 0;" ::: "memory")

// ---------------------------------------------------------------------------
// conv_wv: Wv[k][n] fp32 -> g_WvH4 packed fp16 plane [n][k]
// ---------------------------------------------------------------------------
__global__ void __launch_bounds__(256) conv_wv(const float* __restrict__ Wv) {
    __shared__ float s[32][65];
    const int tid = threadIdx.x;
    const int n0  = blockIdx.x * 32;
    uint2* WvH2 = (uint2*)g_WvH4;

    for (int k0 = 0; k0 < DD; k0 += 64) {
        __syncthreads();
        #pragma unroll
        for (int j = 0; j < 8; ++j) {
            const int idx = tid + j*256;
            const int k = idx >> 5, n = idx & 31;
            s[n][k] = Wv[(size_t)(k0 + k)*AA + n0 + n];
        }
        __syncthreads();
        #pragma unroll
        for (int j = 0; j < 2; ++j) {
            const int i = tid + j*256;           // 32n x 16 slots
            const int n = i >> 4, q = i & 15;
            const int c = q >> 2, t = q & 3;
            const int kl = c*16 + 2*t;
            uint2 w;
            w.x = pack2h(s[n][kl],   s[n][kl+1]);
            w.y = pack2h(s[n][kl+8], s[n][kl+9]);
            WvH2[(size_t)(n0 + n)*128 + (k0/16 + c)*4 + t] = w;
        }
    }
}

// ---------------------------------------------------------------------------
// K1: hidden = dh@Wh + bh (+bv stored);  g_sh = st@Ws + bs + hidden
// grid (4 a-tiles x 32 b-tiles) = 128 blocks; tile 8b x 128a; BK=32.
// Register double-buffer: store(cur) -> prefetch(next) -> compute(cur).
// ---------------------------------------------------------------------------
__global__ void __launch_bounds__(256) k_prep(
    const float* __restrict__ dh, const float* __restrict__ st,
    const float* __restrict__ Wh, const float* __restrict__ bh,
    const float* __restrict__ Ws, const float* __restrict__ bs,
    const float* __restrict__ bv)
{
    __shared__ float dh_s[8][33], st_s[8][33];
    __shared__ float Wh_s[32][128], Ws_s[32][128];
    const int tid = threadIdx.x;
    const int b0  = blockIdx.y * 8;
    const int a0  = blockIdx.x * 128;
    const int al  = tid & 127;
    const int bl  = (tid >> 7) * 4;      // batches bl..bl+3

    float acch[4] = {}, accs[4] = {};

    float4 pwh[4], pws[4];
    float  pdh, pst;
    const int wkk = tid >> 5, wnq = tid & 31;
    const int dbb = tid >> 5, dkk = tid & 31;

    #pragma unroll
    for (int j = 0; j < 4; ++j) {
        pwh[j] = *(const float4*)&Wh[(size_t)(wkk + j*8)*AA + a0 + wnq*4];
        pws[j] = *(const float4*)&Ws[(size_t)(wkk + j*8)*AA + a0 + wnq*4];
    }
    pdh = dh[(b0 + dbb)*DD + dkk];
    pst = st[(b0 + dbb)*DD + dkk];

    for (int kb = 0; kb < DD; kb += 32) {
        __syncthreads();
        dh_s[dbb][dkk] = pdh;
        st_s[dbb][dkk] = pst;
        #pragma unroll
        for (int j = 0; j < 4; ++j) {
            *(float4*)&Wh_s[wkk + j*8][wnq*4] = pwh[j];
            *(float4*)&Ws_s[wkk + j*8][wnq*4] = pws[j];
        }
        __syncthreads();
        if (kb + 32 < DD) {
            #pragma unroll
            for (int j = 0; j < 4; ++j) {
                pwh[j] = *(const float4*)&Wh[(size_t)(kb + 32 + wkk + j*8)*AA + a0 + wnq*4];
                pws[j] = *(const float4*)&Ws[(size_t)(kb + 32 + wkk + j*8)*AA + a0 + wnq*4];
            }
            pdh = dh[(b0 + dbb)*DD + kb + 32 + dkk];
            pst = st[(b0 + dbb)*DD + kb + 32 + dkk];
        }
        #pragma unroll 4
        for (int k = 0; k < 32; ++k) {
            const float wh = Wh_s[k][al], ws = Ws_s[k][al];
            #pragma unroll
            for (int bi = 0; bi < 4; ++bi) {
                acch[bi] += dh_s[bl+bi][k] * wh;
                accs[bi] += st_s[bl+bi][k] * ws;
            }
        }
    }
    #pragma unroll
    for (int bi = 0; bi < 4; ++bi) {
        const int b = b0 + bl + bi, a = a0 + al;
        const float h = acch[bi] + bh[a];
        g_hidden[(size_t)b*AA + a] = h + bv[a];
        g_sh[(size_t)b*AA + a]     = accs[bi] + bs[a] + h;
    }
}

// ---------------------------------------------------------------------------
// K2: z[m] = bav + sum_a Wav[a]*tanh( enc[m,:]@Wv[:,a] + hidden[b(m),a] )
// fp16 m16n8k16, SINGLE pass (A and B both single fp16).
// BM=128, BN=256 (nt=2), BK=32; 512 thr / 16 warps (4m x 4n), warp 32x64.
// Double-buffered smem; per stage: cp.async B(next) + LDG A(next) ->
// compute(cur) -> STS A(next) -> cp.wait -> ONE sync.
// ---------------------------------------------------------------------------
#define ASTR 12              // uint2 per A row (8 used + 4 pad)
#define BSTR 12              // uint2 per B row
// per-buffer layout (bytes): Ah 0, Bh 12288; size 36864
#define BUFSZ   36864
#define OFF_H0  73728
#define OFF_H1  74752
#define OFF_WAV 75776
#define OFF_ZS  76800
#define K2_SMEM 77312

__global__ void __launch_bounds__(512, 1) k_zgemm(
    const float* __restrict__ enc, const float* __restrict__ Wav,
    const float* __restrict__ bav)
{
    extern __shared__ unsigned char sm[];
    float* h0s  = (float*)(sm + OFF_H0);
    float* h1s  = (float*)(sm + OFF_H1);
    float* wavs = (float*)(sm + OFF_WAV);
    float* zs   = (float*)(sm + OFF_ZS);
    const uint32_t sbase = (uint32_t)__cvta_generic_to_shared(sm);

    const int tid  = threadIdx.x, lane = tid & 31, wid = tid >> 5;
    const int wm   = wid & 3;
    const int wn   = wid >> 2;
    const int gid  = lane >> 2, tig = lane & 3;
    const int m0   = blockIdx.x * 128;
    const int b0   = m0 / PP;
    const int b1   = (m0 + 127) / PP;
    const int bsplit = (b0 + 1) * PP;

    int sr_[2], sq_[2], skl_[2];
    #pragma unroll
    for (int j = 0; j < 2; ++j) {
        const int slot = tid + j*512;
        sr_[j]  = slot >> 3;
        sq_[j]  = slot & 7;
        skl_[j] = ((sq_[j] >> 2) << 4) + ((sq_[j] & 3) << 1);
    }
    int bn_[2], bs4_[2];
    #pragma unroll
    for (int j = 0; j < 2; ++j) {
        const int i = tid + j*512;
        bn_[j]  = i >> 2;
        bs4_[j] = i & 3;
    }

    if (tid < 128) zs[tid] = 0.f;

    for (int nt = 0; nt < 2; ++nt) {
        const int n0 = nt * 256;
        __syncthreads();
        for (int i = tid; i < 256; i += 512) {
            wavs[i] = Wav[n0 + i];
            h0s[i]  = g_hidden[(size_t)b0*AA + n0 + i];
            h1s[i]  = g_hidden[(size_t)b1*AA + n0 + i];
        }

        float acc[2][8][4];
        #pragma unroll
        for (int mi = 0; mi < 2; ++mi)
            #pragma unroll
            for (int ni = 0; ni < 8; ++ni)
                #pragma unroll
                for (int q = 0; q < 4; ++q) acc[mi][ni][q] = 0.f;

        // ---- prologue: stage kb=0 into buffer 0 ----
        {
            #pragma unroll
            for (int j = 0; j < 2; ++j) {
                const uint32_t dst = sbase + 12288u + bn_[j]*96u + bs4_[j]*16u;
                cpasync16(dst, &g_WvH4[(size_t)(n0 + bn_[j])*64 + bs4_[j]]);
            }
            CP_COMMIT();
            float2 pa[2][2];
            #pragma unroll
            for (int j = 0; j < 2; ++j) {
                const float* base = &enc[(size_t)(m0 + sr_[j])*DD + skl_[j]];
                pa[j][0] = *(const float2*)(base);
                pa[j][1] = *(const float2*)(base + 8);
            }
            uint2* Ah = (uint2*)(sm);
            #pragma unroll
            for (int j = 0; j < 2; ++j) {
                const int u = sr_[j]*ASTR + sq_[j];
                Ah[u] = make_uint2(pack2h(pa[j][0].x, pa[j][0].y),
                                   pack2h(pa[j][1].x, pa[j][1].y));
            }
            CP_WAIT0();
        }
        __syncthreads();

        int cur = 0;
        for (int kb = 0; kb < DD; kb += 32) {
            const int has_next = (kb + 32 < DD);
            const int nxt = cur ^ 1;
            float2 pa[2][2];
            if (has_next) {
                const int kc = ((kb + 32) >> 4) * 2;
                #pragma unroll
                for (int j = 0; j < 2; ++j) {
                    const uint32_t dst = sbase + (uint32_t)nxt*BUFSZ +
                        12288u + bn_[j]*96u + bs4_[j]*16u;
                    cpasync16(dst, &g_WvH4[(size_t)(n0 + bn_[j])*64 + kc + bs4_[j]]);
                }
                CP_COMMIT();
                #pragma unroll
                for (int j = 0; j < 2; ++j) {
                    const float* base =
                        &enc[(size_t)(m0 + sr_[j])*DD + kb + 32 + skl_[j]];
                    pa[j][0] = *(const float2*)(base);
                    pa[j][1] = *(const float2*)(base + 8);
                }
            }

            // ---- compute on buf[cur] ----
            {
                uint2* Ah = (uint2*)(sm + cur*BUFSZ);
                uint2* Bh = (uint2*)(sm + cur*BUFSZ + 12288);
                #pragma unroll
                for (int c = 0; c < 2; ++c) {
                    uint32_t ah[2][4];
                    #pragma unroll
                    for (int mi = 0; mi < 2; ++mi) {
                        const int r = wm*32 + mi*16 + gid;
                        const uint2 u0 = Ah[(r    )*ASTR + c*4 + tig];
                        const uint2 u1 = Ah[(r + 8)*ASTR + c*4 + tig];
                        ah[mi][0] = u0.x; ah[mi][1] = u1.x;
                        ah[mi][2] = u0.y; ah[mi][3] = u1.y;
                    }
                    #pragma unroll
                    for (int ni = 0; ni < 8; ++ni) {
                        const int n = wn*64 + ni*8 + gid;
                        const uint2 ubh = Bh[n*BSTR + c*4 + tig];
                        const uint32_t bhf[2] = {ubh.x, ubh.y};
                        #pragma unroll
                        for (int mi = 0; mi < 2; ++mi)
                            mma16h(acc[mi][ni], ah[mi], bhf);
                    }
                }
            }

            if (has_next) {
                uint2* Ah = (uint2*)(sm + nxt*BUFSZ);
                #pragma unroll
                for (int j = 0; j < 2; ++j) {
                    const int u = sr_[j]*ASTR + sq_[j];
                    Ah[u] = make_uint2(pack2h(pa[j][0].x, pa[j][0].y),
                                       pack2h(pa[j][1].x, pa[j][1].y));
                }
                CP_WAIT0();
            }
            __syncthreads();
            cur = nxt;
        }

        // ---- epilogue: tanh(v + hidden) * Wav, row partial sums ----
        float rs[2][2] = {0.f, 0.f, 0.f, 0.f};
        #pragma unroll
        for (int mi = 0; mi < 2; ++mi) {
            const int r_lo = m0 + wm*32 + mi*16 + gid;
            const float* hlo = (r_lo     >= bsplit) ? h1s : h0s;
            const float* hhi = (r_lo + 8 >= bsplit) ? h1s : h0s;
            #pragma unroll
            for (int ni = 0; ni < 8; ++ni) {
                const int c0 = wn*64 + ni*8 + 2*tig;
                const float w0 = wavs[c0], w1 = wavs[c0+1];
                rs[mi][0] += tanhapx(acc[mi][ni][0] + hlo[c0  ]) * w0
                           + tanhapx(acc[mi][ni][1] + hlo[c0+1]) * w1;
                rs[mi][1] += tanhapx(acc[mi][ni][2] + hhi[c0  ]) * w0
                           + tanhapx(acc[mi][ni][3] + hhi[c0+1]) * w1;
            }
        }
        #pragma unroll
        for (int off = 1; off <= 2; off <<= 1) {
            #pragma unroll
            for (int mi = 0; mi < 2; ++mi) {
                rs[mi][0] += __shfl_xor_sync(0xffffffffu, rs[mi][0], off);
                rs[mi][1] += __shfl_xor_sync(0xffffffffu, rs[mi][1], off);
            }
        }
        if (tig == 0) {
            #pragma unroll
            for (int mi = 0; mi < 2; ++mi) {
                atomicAdd(&zs[wm*32 + mi*16 + gid    ], rs[mi][0]);
                atomicAdd(&zs[wm*32 + mi*16 + gid + 8], rs[mi][1]);
            }
        }
    }
    __syncthreads();
    if (tid < 128) g_z[m0 + tid] = zs[tid] + bav[0];
}

// ---------------------------------------------------------------------------
// K3: s_att reduce; softmax; beta; c_t; gated output
// grid (B, 4): 128 d's/block. c_t: 32 d-quads x 8 p-groups, float4-coalesced.
// ---------------------------------------------------------------------------
__global__ void __launch_bounds__(256) k_soft(
    const float* __restrict__ enc, const float* __restrict__ st,
    const float* __restrict__ Was, const float* __restrict__ bas,
    float* __restrict__ out)
{
    __shared__ float zsh[PP];
    __shared__ float alpha_sh[PP];
    __shared__ float red[256];
    __shared__ float4 red4[8][32];
    const int tid = threadIdx.x;
    const int b   = blockIdx.x;
    const int y   = blockIdx.y;

    float sacc = 0.f;
    for (int i = tid; i < AA; i += 256)
        sacc += tanhapx(g_sh[(size_t)b*AA + i]) * Was[i];
    red[tid] = sacc;
    __syncthreads();
    for (int s = 128; s > 0; s >>= 1) {
        if (tid < s) red[tid] += red[tid + s];
        __syncthreads();
    }
    const float sa = red[0] + bas[0];
    __syncthreads();

    if (tid < PP) zsh[tid] = g_z[b*PP + tid];
    __syncthreads();

    red[tid] = (tid < PP) ? zsh[tid] : -1e30f;
    __syncthreads();
    for (int s = 128; s > 0; s >>= 1) {
        if (tid < s) red[tid] = fmaxf(red[tid], red[tid + s]);
        __syncthreads();
    }
    const float m1 = red[0];
    __syncthreads();

    const float e = (tid < PP) ? __expf(zsh[tid] - m1) : 0.f;
    red[tid] = e;
    __syncthreads();
    for (int s = 128; s > 0; s >>= 1) {
        if (tid < s) red[tid] += red[tid + s];
        __syncthreads();
    }
    const float sum1 = red[0];

    if (tid < PP) {
        const float alpha = e / sum1;
        alpha_sh[tid] = alpha;
        if (y == 0) out[BB*DD + b*PP + tid] = alpha;     // alpha_t
    }

    const float m2   = fmaxf(m1, sa);
    const float sum2 = sum1 * __expf(m1 - m2) + __expf(sa - m2);
    const float beta = __expf(sa - m2) / sum2;
    if (y == 0 && tid == 0) out[BB*DD + BB*PP + b] = beta;  // beta_t
    __syncthreads();

    // c_t: 32 d-quads x 8 p-groups; warp = one p-group, fully coalesced.
    const int q  = tid & 31;
    const int g  = tid >> 5;
    const int d4 = y*128 + q*4;
    const float* eb = enc + (size_t)b*PP*DD + d4;
    float4 a4 = make_float4(0.f, 0.f, 0.f, 0.f);
    #pragma unroll 4
    for (int p = g; p < PP; p += 8) {
        const float4 ev = *(const float4*)(eb + (size_t)p*DD);
        const float al = alpha_sh[p];
        a4.x += ev.x*al; a4.y += ev.y*al; a4.z += ev.z*al; a4.w += ev.w*al;
    }
    red4[g][q] = a4;
    __syncthreads();
    #pragma unroll
    for (int s = 4; s > 0; s >>= 1) {
        if (g < s) {
            float4 o = red4[g + s][q];
            a4.x += o.x; a4.y += o.y; a4.z += o.z; a4.w += o.w;
            red4[g][q] = a4;
        }
        __syncthreads();
    }
    if (g == 0) {
        const float4 s4 = *(const float4*)&st[b*DD + d4];
        float4 o;
        o.x = beta*s4.x + (1.f - beta)*a4.x;
        o.y = beta*s4.y + (1.f - beta)*a4.y;
        o.z = beta*s4.z + (1.f - beta)*a4.z;
        o.w = beta*s4.w + (1.f - beta)*a4.w;
        *(float4*)&out[b*DD + d4] = o;                   // c_hat_t
    }
}

// ---------------------------------------------------------------------------
extern "C" void kernel_launch(void* const* d_in, const int* in_sizes, int n_in,
                              void* d_out, int out_size) {
    const float* enc = (const float*)d_in[0];
    const float* dh  = (const float*)d_in[1];
    const float* st  = (const float*)d_in[2];
    const float* Wv  = (const float*)d_in[3];
    const float* bv  = (const float*)d_in[4];
    const float* Wh  = (const float*)d_in[5];
    const float* bh  = (const float*)d_in[6];
    const float* Ws  = (const float*)d_in[7];
    const float* bs  = (const float*)d_in[8];
    const float* Wav = (const float*)d_in[9];
    const float* bav = (const float*)d_in[10];
    const float* Was = (const float*)d_in[11];
    const float* bas = (const float*)d_in[12];
    float* out = (float*)d_out;

    static int smem_set = 0;
    if (!smem_set) {
        cudaFuncSetAttribute(k_zgemm,
            cudaFuncAttributeMaxDynamicSharedMemorySize, K2_SMEM);
        smem_set = 1;
    }

    conv_wv<<<16, 256>>>(Wv);
    k_prep <<<dim3(4, 32), 256>>>(dh, st, Wh, bh, Ws, bs, bv);
    k_zgemm<<<MM/128, 512, K2_SMEM>>>(enc, Wav, bav);
    k_soft <<<dim3(BB, 4), 256>>>(enc, st, Was, bas, out);
}

// round 15
// speedup vs baseline: 4.1426x; 1.0462x over previous
#include <cuda_runtime.h>
#include <cuda_fp16.h>
#include <cstdint>

#define BB 256
#define PP 196
#define DD 512
#define AA 512
#define MM (BB*PP)   // 50176

// ---------------- scratch (__device__ globals; no allocs) -------------------
__device__ float g_hidden[BB*AA];      // hidden + bv
__device__ float g_sh[BB*AA];          // st@Ws + bs + hidden (pre-tanh)
__device__ float g_z[BB*PP];           // logits -> (after k_alpha) alpha
__device__ float g_beta[BB];           // gate
// Wv^T fp16 plane, fragment-packed: [n(512)][chunk c(32)][slot t(4)] uint2
// slot t of chunk c = { f16pair(k=16c+2t), f16pair(k=16c+2t+8) }
__device__ uint4 g_WvH4[512*64];       // 512KB

// ---------------- helpers ---------------------------------------------------
__device__ __forceinline__ float tanhapx(float x) {
    float y; asm("tanh.approx.f32 %0, %1;" : "=f"(y) : "f"(x)); return y;
}
__device__ __forceinline__ uint32_t pack2h(float a, float b) {
    const __half ha = __float2half(a), hb = __float2half(b);
    return (uint32_t)__half_as_ushort(ha) |
           ((uint32_t)__half_as_ushort(hb) << 16);
}
__device__ __forceinline__ void mma16h(float* c, const uint32_t* a, const uint32_t* b) {
    asm volatile(
        "mma.sync.aligned.m16n8k16.row.col.f32.f16.f16.f32 "
        "{%0,%1,%2,%3}, {%4,%5,%6,%7}, {%8,%9}, {%0,%1,%2,%3};"
        : "+f"(c[0]), "+f"(c[1]), "+f"(c[2]), "+f"(c[3])
        : "r"(a[0]), "r"(a[1]), "r"(a[2]), "r"(a[3]), "r"(b[0]), "r"(b[1]));
}
__device__ __forceinline__ void cpasync16(uint32_t dst, const void* src) {
    asm volatile("cp.async.ca.shared.global [%0], [%1], 16;" :: "r"(dst), "l"(src));
}
#define CP_COMMIT() asm volatile("cp.async.commit_group;" ::: "memory")
#define CP_WAIT0()  asm volatile("cp.async.wait_group 0;" ::: "memory")

// ---------------------------------------------------------------------------
// conv_wv: Wv[k][n] fp32 -> g_WvH4 packed fp16 plane [n][k]
// ---------------------------------------------------------------------------
__global__ void __launch_bounds__(256) conv_wv(const float* __restrict__ Wv) {
    __shared__ float s[32][65];
    const int tid = threadIdx.x;
    const int n0  = blockIdx.x * 32;
    uint2* WvH2 = (uint2*)g_WvH4;

    for (int k0 = 0; k0 < DD; k0 += 64) {
        __syncthreads();
        #pragma unroll
        for (int j = 0; j < 8; ++j) {
            const int idx = tid + j*256;
            const int k = idx >> 5, n = idx & 31;
            s[n][k] = Wv[(size_t)(k0 + k)*AA + n0 + n];
        }
        __syncthreads();
        #pragma unroll
        for (int j = 0; j < 2; ++j) {
            const int i = tid + j*256;           // 32n x 16 slots
            const int n = i >> 4, q = i & 15;
            const int c = q >> 2, t = q & 3;
            const int kl = c*16 + 2*t;
            uint2 w;
            w.x = pack2h(s[n][kl],   s[n][kl+1]);
            w.y = pack2h(s[n][kl+8], s[n][kl+9]);
            WvH2[(size_t)(n0 + n)*128 + (k0/16 + c)*4 + t] = w;
        }
    }
}

// ---------------------------------------------------------------------------
// K1: hidden = dh@Wh + bh (+bv stored);  g_sh = st@Ws + bs + hidden
// grid (4 a-tiles x 32 b-tiles) = 128 blocks; tile 8b x 128a; BK=32.
// ---------------------------------------------------------------------------
__global__ void __launch_bounds__(256) k_prep(
    const float* __restrict__ dh, const float* __restrict__ st,
    const float* __restrict__ Wh, const float* __restrict__ bh,
    const float* __restrict__ Ws, const float* __restrict__ bs,
    const float* __restrict__ bv)
{
    __shared__ float dh_s[8][33], st_s[8][33];
    __shared__ float Wh_s[32][128], Ws_s[32][128];
    const int tid = threadIdx.x;
    const int b0  = blockIdx.y * 8;
    const int a0  = blockIdx.x * 128;
    const int al  = tid & 127;
    const int bl  = (tid >> 7) * 4;

    float acch[4] = {}, accs[4] = {};

    float4 pwh[4], pws[4];
    float  pdh, pst;
    const int wkk = tid >> 5, wnq = tid & 31;
    const int dbb = tid >> 5, dkk = tid & 31;

    #pragma unroll
    for (int j = 0; j < 4; ++j) {
        pwh[j] = *(const float4*)&Wh[(size_t)(wkk + j*8)*AA + a0 + wnq*4];
        pws[j] = *(const float4*)&Ws[(size_t)(wkk + j*8)*AA + a0 + wnq*4];
    }
    pdh = dh[(b0 + dbb)*DD + dkk];
    pst = st[(b0 + dbb)*DD + dkk];

    for (int kb = 0; kb < DD; kb += 32) {
        __syncthreads();
        dh_s[dbb][dkk] = pdh;
        st_s[dbb][dkk] = pst;
        #pragma unroll
        for (int j = 0; j < 4; ++j) {
            *(float4*)&Wh_s[wkk + j*8][wnq*4] = pwh[j];
            *(float4*)&Ws_s[wkk + j*8][wnq*4] = pws[j];
        }
        __syncthreads();
        if (kb + 32 < DD) {
            #pragma unroll
            for (int j = 0; j < 4; ++j) {
                pwh[j] = *(const float4*)&Wh[(size_t)(kb + 32 + wkk + j*8)*AA + a0 + wnq*4];
                pws[j] = *(const float4*)&Ws[(size_t)(kb + 32 + wkk + j*8)*AA + a0 + wnq*4];
            }
            pdh = dh[(b0 + dbb)*DD + kb + 32 + dkk];
            pst = st[(b0 + dbb)*DD + kb + 32 + dkk];
        }
        #pragma unroll 4
        for (int k = 0; k < 32; ++k) {
            const float wh = Wh_s[k][al], ws = Ws_s[k][al];
            #pragma unroll
            for (int bi = 0; bi < 4; ++bi) {
                acch[bi] += dh_s[bl+bi][k] * wh;
                accs[bi] += st_s[bl+bi][k] * ws;
            }
        }
    }
    #pragma unroll
    for (int bi = 0; bi < 4; ++bi) {
        const int b = b0 + bl + bi, a = a0 + al;
        const float h = acch[bi] + bh[a];
        g_hidden[(size_t)b*AA + a] = h + bv[a];
        g_sh[(size_t)b*AA + a]     = accs[bi] + bs[a] + h;
    }
}

// ---------------------------------------------------------------------------
// K2: z[m] = bav + sum_a Wav[a]*tanh( enc[m,:]@Wv[:,a] + hidden[b(m),a] )
// fp16 m16n8k16 single pass. BM=128, BN=256 (nt=2), BK=64 (8 stages/nt);
// 512 thr / 16 warps (4m x 4n), warp 32x64. Double-buffered smem + cp.async.
// ---------------------------------------------------------------------------
#define ASTR 20              // uint2 per A row (16 used + 4 pad)
#define BSTR 20              // uint2 per B row (16 used + 4 pad)
// per-buffer layout (bytes): Ah 0 (128*20*8=20480), Bh 20480 (256*20*8=40960)
#define BUFSZ   61440
#define OFF_H0  122880
#define OFF_H1  123904
#define OFF_WAV 124928
#define OFF_ZS  125952
#define K2_SMEM 126464

__global__ void __launch_bounds__(512, 1) k_zgemm(
    const float* __restrict__ enc, const float* __restrict__ Wav,
    const float* __restrict__ bav)
{
    extern __shared__ unsigned char sm[];
    float* h0s  = (float*)(sm + OFF_H0);
    float* h1s  = (float*)(sm + OFF_H1);
    float* wavs = (float*)(sm + OFF_WAV);
    float* zs   = (float*)(sm + OFF_ZS);
    const uint32_t sbase = (uint32_t)__cvta_generic_to_shared(sm);

    const int tid  = threadIdx.x, lane = tid & 31, wid = tid >> 5;
    const int wm   = wid & 3;
    const int wn   = wid >> 2;
    const int gid  = lane >> 2, tig = lane & 3;
    const int m0   = blockIdx.x * 128;
    const int b0   = m0 / PP;
    const int b1   = (m0 + 127) / PP;
    const int bsplit = (b0 + 1) * PP;

    // A staging slots (4 per thread): 128 rows x 16 q-slots
    int sr_[4], sq_[4], skl_[4];
    #pragma unroll
    for (int j = 0; j < 4; ++j) {
        const int slot = tid + j*512;         // 0..2047
        sr_[j]  = slot >> 4;
        sq_[j]  = slot & 15;
        skl_[j] = ((sq_[j] >> 2) << 4) + ((sq_[j] & 3) << 1);   // 16c + 2t
    }
    // B staging slots (4 per thread): 256 n x 8 uint4 chunks
    int bn_[4], bs8_[4];
    #pragma unroll
    for (int j = 0; j < 4; ++j) {
        const int i = tid + j*512;            // 0..2047
        bn_[j]  = i >> 3;
        bs8_[j] = i & 7;
    }

    if (tid < 128) zs[tid] = 0.f;

    for (int nt = 0; nt < 2; ++nt) {
        const int n0 = nt * 256;
        __syncthreads();
        for (int i = tid; i < 256; i += 512) {
            wavs[i] = Wav[n0 + i];
            h0s[i]  = g_hidden[(size_t)b0*AA + n0 + i];
            h1s[i]  = g_hidden[(size_t)b1*AA + n0 + i];
        }

        float acc[2][8][4];
        #pragma unroll
        for (int mi = 0; mi < 2; ++mi)
            #pragma unroll
            for (int ni = 0; ni < 8; ++ni)
                #pragma unroll
                for (int q = 0; q < 4; ++q) acc[mi][ni][q] = 0.f;

        // ---- prologue: stage kb=0 into buffer 0 ----
        {
            #pragma unroll
            for (int j = 0; j < 4; ++j) {
                const uint32_t dst = sbase + 20480u + bn_[j]*160u + bs8_[j]*16u;
                cpasync16(dst, &g_WvH4[(size_t)(n0 + bn_[j])*64 + bs8_[j]]);
            }
            CP_COMMIT();
            float2 pa[4][2];
            #pragma unroll
            for (int j = 0; j < 4; ++j) {
                const float* base = &enc[(size_t)(m0 + sr_[j])*DD + skl_[j]];
                pa[j][0] = *(const float2*)(base);
                pa[j][1] = *(const float2*)(base + 8);
            }
            uint2* Ah = (uint2*)(sm);
            #pragma unroll
            for (int j = 0; j < 4; ++j) {
                const int u = sr_[j]*ASTR + sq_[j];
                Ah[u] = make_uint2(pack2h(pa[j][0].x, pa[j][0].y),
                                   pack2h(pa[j][1].x, pa[j][1].y));
            }
            CP_WAIT0();
        }
        __syncthreads();

        int cur = 0;
        for (int kb = 0; kb < DD; kb += 64) {
            const int has_next = (kb + 64 < DD);
            const int nxt = cur ^ 1;
            float2 pa[4][2];
            if (has_next) {
                const int kc = ((kb + 64) >> 4) * 2;
                #pragma unroll
                for (int j = 0; j < 4; ++j) {
                    const uint32_t dst = sbase + (uint32_t)nxt*BUFSZ +
                        20480u + bn_[j]*160u + bs8_[j]*16u;
                    cpasync16(dst, &g_WvH4[(size_t)(n0 + bn_[j])*64 + kc + bs8_[j]]);
                }
                CP_COMMIT();
                #pragma unroll
                for (int j = 0; j < 4; ++j) {
                    const float* base =
                        &enc[(size_t)(m0 + sr_[j])*DD + kb + 64 + skl_[j]];
                    pa[j][0] = *(const float2*)(base);
                    pa[j][1] = *(const float2*)(base + 8);
                }
            }

            // ---- compute on buf[cur]: 4 k16 steps ----
            {
                uint2* Ah = (uint2*)(sm + cur*BUFSZ);
                uint2* Bh = (uint2*)(sm + cur*BUFSZ + 20480);
                #pragma unroll
                for (int c = 0; c < 4; ++c) {
                    uint32_t ah[2][4];
                    #pragma unroll
                    for (int mi = 0; mi < 2; ++mi) {
                        const int r = wm*32 + mi*16 + gid;
                        const uint2 u0 = Ah[(r    )*ASTR + c*4 + tig];
                        const uint2 u1 = Ah[(r + 8)*ASTR + c*4 + tig];
                        ah[mi][0] = u0.x; ah[mi][1] = u1.x;
                        ah[mi][2] = u0.y; ah[mi][3] = u1.y;
                    }
                    #pragma unroll
                    for (int ni = 0; ni < 8; ++ni) {
                        const int n = wn*64 + ni*8 + gid;
                        const uint2 ubh = Bh[n*BSTR + c*4 + tig];
                        const uint32_t bhf[2] = {ubh.x, ubh.y};
                        #pragma unroll
                        for (int mi = 0; mi < 2; ++mi)
                            mma16h(acc[mi][ni], ah[mi], bhf);
                    }
                }
            }

            if (has_next) {
                uint2* Ah = (uint2*)(sm + nxt*BUFSZ);
                #pragma unroll
                for (int j = 0; j < 4; ++j) {
                    const int u = sr_[j]*ASTR + sq_[j];
                    Ah[u] = make_uint2(pack2h(pa[j][0].x, pa[j][0].y),
                                       pack2h(pa[j][1].x, pa[j][1].y));
                }
                CP_WAIT0();
            }
            __syncthreads();
            cur = nxt;
        }

        // ---- epilogue: tanh(v + hidden) * Wav, row partial sums ----
        float rs[2][2] = {0.f, 0.f, 0.f, 0.f};
        #pragma unroll
        for (int mi = 0; mi < 2; ++mi) {
            const int r_lo = m0 + wm*32 + mi*16 + gid;
            const float* hlo = (r_lo     >= bsplit) ? h1s : h0s;
            const float* hhi = (r_lo + 8 >= bsplit) ? h1s : h0s;
            #pragma unroll
            for (int ni = 0; ni < 8; ++ni) {
                const int c0 = wn*64 + ni*8 + 2*tig;
                const float w0 = wavs[c0], w1 = wavs[c0+1];
                rs[mi][0] += tanhapx(acc[mi][ni][0] + hlo[c0  ]) * w0
                           + tanhapx(acc[mi][ni][1] + hlo[c0+1]) * w1;
                rs[mi][1] += tanhapx(acc[mi][ni][2] + hhi[c0  ]) * w0
                           + tanhapx(acc[mi][ni][3] + hhi[c0+1]) * w1;
            }
        }
        #pragma unroll
        for (int off = 1; off <= 2; off <<= 1) {
            #pragma unroll
            for (int mi = 0; mi < 2; ++mi) {
                rs[mi][0] += __shfl_xor_sync(0xffffffffu, rs[mi][0], off);
                rs[mi][1] += __shfl_xor_sync(0xffffffffu, rs[mi][1], off);
            }
        }
        if (tig == 0) {
            #pragma unroll
            for (int mi = 0; mi < 2; ++mi) {
                atomicAdd(&zs[wm*32 + mi*16 + gid    ], rs[mi][0]);
                atomicAdd(&zs[wm*32 + mi*16 + gid + 8], rs[mi][1]);
            }
        }
    }
    __syncthreads();
    if (tid < 128) g_z[m0 + tid] = zs[tid] + bav[0];
}

// ---------------------------------------------------------------------------
// K3a: per-batch s_att + softmax + beta. Rewrites g_z with alpha; writes
// alpha_t and beta_t outputs and g_beta.
// ---------------------------------------------------------------------------
__global__ void __launch_bounds__(256) k_alpha(
    const float* __restrict__ Was, const float* __restrict__ bas,
    float* __restrict__ out)
{
    __shared__ float zsh[PP];
    __shared__ float red[256];
    const int tid = threadIdx.x;
    const int b   = blockIdx.x;

    float sacc = 0.f;
    for (int i = tid; i < AA; i += 256)
        sacc += tanhapx(g_sh[(size_t)b*AA + i]) * Was[i];
    red[tid] = sacc;
    __syncthreads();
    for (int s = 128; s > 0; s >>= 1) {
        if (tid < s) red[tid] += red[tid + s];
        __syncthreads();
    }
    const float sa = red[0] + bas[0];
    __syncthreads();

    if (tid < PP) zsh[tid] = g_z[b*PP + tid];
    __syncthreads();

    red[tid] = (tid < PP) ? zsh[tid] : -1e30f;
    __syncthreads();
    for (int s = 128; s > 0; s >>= 1) {
        if (tid < s) red[tid] = fmaxf(red[tid], red[tid + s]);
        __syncthreads();
    }
    const float m1 = red[0];
    __syncthreads();

    const float e = (tid < PP) ? __expf(zsh[tid] - m1) : 0.f;
    red[tid] = e;
    __syncthreads();
    for (int s = 128; s > 0; s >>= 1) {
        if (tid < s) red[tid] += red[tid + s];
        __syncthreads();
    }
    const float sum1 = red[0];

    if (tid < PP) {
        const float alpha = e / sum1;
        g_z[b*PP + tid] = alpha;                 // overwrite logits with alpha
        out[BB*DD + b*PP + tid] = alpha;         // alpha_t
    }

    const float m2   = fmaxf(m1, sa);
    const float sum2 = sum1 * __expf(m1 - m2) + __expf(sa - m2);
    const float beta = __expf(sa - m2) / sum2;
    if (tid == 0) {
        g_beta[b] = beta;
        out[BB*DD + BB*PP + b] = beta;           // beta_t
    }
}

// ---------------------------------------------------------------------------
// K3b: c_t = enc^T alpha ; c_hat = beta*st + (1-beta)*c_t. Pure streaming.
// grid (B, 4): 128 d's/block; 32 d-quads x 8 p-groups, float4-coalesced.
// ---------------------------------------------------------------------------
__global__ void __launch_bounds__(256) k_ct(
    const float* __restrict__ enc, const float* __restrict__ st,
    float* __restrict__ out)
{
    __shared__ float alpha_sh[PP];
    __shared__ float4 red4[8][32];
    const int tid = threadIdx.x;
    const int b   = blockIdx.x;
    const int y   = blockIdx.y;

    if (tid < PP) alpha_sh[tid] = g_z[b*PP + tid];
    __syncthreads();
    const float beta = g_beta[b];

    const int q  = tid & 31;
    const int g  = tid >> 5;
    const int d4 = y*128 + q*4;
    const float* eb = enc + (size_t)b*PP*DD + d4;
    float4 a4 = make_float4(0.f, 0.f, 0.f, 0.f);
    #pragma unroll 4
    for (int p = g; p < PP; p += 8) {
        const float4 ev = *(const float4*)(eb + (size_t)p*DD);
        const float al = alpha_sh[p];
        a4.x += ev.x*al; a4.y += ev.y*al; a4.z += ev.z*al; a4.w += ev.w*al;
    }
    red4[g][q] = a4;
    __syncthreads();
    #pragma unroll
    for (int s = 4; s > 0; s >>= 1) {
        if (g < s) {
            float4 o = red4[g + s][q];
            a4.x += o.x; a4.y += o.y; a4.z += o.z; a4.w += o.w;
            red4[g][q] = a4;
        }
        __syncthreads();
    }
    if (g == 0) {
        const float4 s4 = *(const float4*)&st[b*DD + d4];
        float4 o;
        o.x = beta*s4.x + (1.f - beta)*a4.x;
        o.y = beta*s4.y + (1.f - beta)*a4.y;
        o.z = beta*s4.z + (1.f - beta)*a4.z;
        o.w = beta*s4.w + (1.f - beta)*a4.w;
        *(float4*)&out[b*DD + d4] = o;           // c_hat_t
    }
}

// ---------------------------------------------------------------------------
extern "C" void kernel_launch(void* const* d_in, const int* in_sizes, int n_in,
                              void* d_out, int out_size) {
    const float* enc = (const float*)d_in[0];
    const float* dh  = (const float*)d_in[1];
    const float* st  = (const float*)d_in[2];
    const float* Wv  = (const float*)d_in[3];
    const float* bv  = (const float*)d_in[4];
    const float* Wh  = (const float*)d_in[5];
    const float* bh  = (const float*)d_in[6];
    const float* Ws  = (const float*)d_in[7];
    const float* bs  = (const float*)d_in[8];
    const float* Wav = (const float*)d_in[9];
    const float* bav = (const float*)d_in[10];
    const float* Was = (const float*)d_in[11];
    const float* bas = (const float*)d_in[12];
    float* out = (float*)d_out;

    static int smem_set = 0;
    if (!smem_set) {
        cudaFuncSetAttribute(k_zgemm,
            cudaFuncAttributeMaxDynamicSharedMemorySize, K2_SMEM);
        smem_set = 1;
    }

    conv_wv<<<16, 256>>>(Wv);
    k_prep <<<dim3(4, 32), 256>>>(dh, st, Wh, bh, Ws, bs, bv);
    k_zgemm<<<MM/128, 512, K2_SMEM>>>(enc, Wav, bav);
    k_alpha<<<BB, 256>>>(Was, bas, out);
    k_ct   <<<dim3(BB, 4), 256>>>(enc, st, out);
}

// round 16
// speedup vs baseline: 4.5796x; 1.1055x over previous
#include <cuda_runtime.h>
#include <cuda_fp16.h>
#include <cstdint>

#define BB 256
#define PP 196
#define DD 512
#define AA 512
#define MM (BB*PP)   // 50176

// ---------------- scratch (__device__ globals; no allocs) -------------------
__device__ float g_hidden[BB*AA];      // hidden + bv
__device__ float g_sh[BB*AA];          // st@Ws + bs + hidden (pre-tanh)
__device__ float g_z[BB*PP];           // logits
// Wv^T fp16 plane, fragment-packed: [n(512)][chunk c(32)][slot t(4)] uint2
// slot t of chunk c = { f16pair(k=16c+2t), f16pair(k=16c+2t+8) }
__device__ uint4 g_WvH4[512*64];       // 512KB

// ---------------- helpers ---------------------------------------------------
__device__ __forceinline__ float tanhapx(float x) {
    float y; asm("tanh.approx.f32 %0, %1;" : "=f"(y) : "f"(x)); return y;
}
__device__ __forceinline__ uint32_t pack2h(float a, float b) {
    const __half ha = __float2half(a), hb = __float2half(b);
    return (uint32_t)__half_as_ushort(ha) |
           ((uint32_t)__half_as_ushort(hb) << 16);
}
__device__ __forceinline__ void mma16h(float* c, const uint32_t* a, const uint32_t* b) {
    asm volatile(
        "mma.sync.aligned.m16n8k16.row.col.f32.f16.f16.f32 "
        "{%0,%1,%2,%3}, {%4,%5,%6,%7}, {%8,%9}, {%0,%1,%2,%3};"
        : "+f"(c[0]), "+f"(c[1]), "+f"(c[2]), "+f"(c[3])
        : "r"(a[0]), "r"(a[1]), "r"(a[2]), "r"(a[3]), "r"(b[0]), "r"(b[1]));
}
__device__ __forceinline__ void cpasync16(uint32_t dst, const void* src) {
    asm volatile("cp.async.ca.shared.global [%0], [%1], 16;" :: "r"(dst), "l"(src));
}
#define CP_COMMIT() asm volatile("cp.async.commit_group;" ::: "memory")
#define CP_WAIT0()  asm volatile("cp.async.wait_group 0;" ::: "memory")

// ---------------------------------------------------------------------------
// K1 fused: blocks 0..127 -> prep (hidden/g_sh GEMMs); 128..143 -> conv_wv.
// Independent inputs/outputs, so both halves run concurrently in one launch.
// ---------------------------------------------------------------------------
__global__ void __launch_bounds__(256) k_prepc(
    const float* __restrict__ dh, const float* __restrict__ st,
    const float* __restrict__ Wh, const float* __restrict__ bh,
    const float* __restrict__ Ws, const float* __restrict__ bs,
    const float* __restrict__ bv, const float* __restrict__ Wv)
{
    __shared__ float dh_s[8][33], st_s[8][33];
    __shared__ float Wh_s[32][128], Ws_s[32][128];
    __shared__ float cv_s[32][65];
    const int tid = threadIdx.x;

    if (blockIdx.x >= 128) {
        // ---- conv_wv: Wv[k][n] fp32 -> packed fp16 plane [n][k] ----
        const int n0 = (blockIdx.x - 128) * 32;
        uint2* WvH2 = (uint2*)g_WvH4;
        for (int k0 = 0; k0 < DD; k0 += 64) {
            __syncthreads();
            #pragma unroll
            for (int j = 0; j < 8; ++j) {
                const int idx = tid + j*256;
                const int k = idx >> 5, n = idx & 31;
                cv_s[n][k] = Wv[(size_t)(k0 + k)*AA + n0 + n];
            }
            __syncthreads();
            #pragma unroll
            for (int j = 0; j < 2; ++j) {
                const int i = tid + j*256;           // 32n x 16 slots
                const int n = i >> 4, q = i & 15;
                const int c = q >> 2, t = q & 3;
                const int kl = c*16 + 2*t;
                uint2 w;
                w.x = pack2h(cv_s[n][kl],   cv_s[n][kl+1]);
                w.y = pack2h(cv_s[n][kl+8], cv_s[n][kl+9]);
                WvH2[(size_t)(n0 + n)*128 + (k0/16 + c)*4 + t] = w;
            }
        }
        return;
    }

    // ---- prep: tile 8b x 128a; BK=32; register double-buffer ----
    const int b0  = (blockIdx.x >> 2) * 8;
    const int a0  = (blockIdx.x & 3) * 128;
    const int al  = tid & 127;
    const int bl  = (tid >> 7) * 4;

    float acch[4] = {}, accs[4] = {};

    float4 pwh[4], pws[4];
    float  pdh, pst;
    const int wkk = tid >> 5, wnq = tid & 31;
    const int dbb = tid >> 5, dkk = tid & 31;

    #pragma unroll
    for (int j = 0; j < 4; ++j) {
        pwh[j] = *(const float4*)&Wh[(size_t)(wkk + j*8)*AA + a0 + wnq*4];
        pws[j] = *(const float4*)&Ws[(size_t)(wkk + j*8)*AA + a0 + wnq*4];
    }
    pdh = dh[(b0 + dbb)*DD + dkk];
    pst = st[(b0 + dbb)*DD + dkk];

    for (int kb = 0; kb < DD; kb += 32) {
        __syncthreads();
        dh_s[dbb][dkk] = pdh;
        st_s[dbb][dkk] = pst;
        #pragma unroll
        for (int j = 0; j < 4; ++j) {
            *(float4*)&Wh_s[wkk + j*8][wnq*4] = pwh[j];
            *(float4*)&Ws_s[wkk + j*8][wnq*4] = pws[j];
        }
        __syncthreads();
        if (kb + 32 < DD) {
            #pragma unroll
            for (int j = 0; j < 4; ++j) {
                pwh[j] = *(const float4*)&Wh[(size_t)(kb + 32 + wkk + j*8)*AA + a0 + wnq*4];
                pws[j] = *(const float4*)&Ws[(size_t)(kb + 32 + wkk + j*8)*AA + a0 + wnq*4];
            }
            pdh = dh[(b0 + dbb)*DD + kb + 32 + dkk];
            pst = st[(b0 + dbb)*DD + kb + 32 + dkk];
        }
        #pragma unroll 4
        for (int k = 0; k < 32; ++k) {
            const float wh = Wh_s[k][al], ws = Ws_s[k][al];
            #pragma unroll
            for (int bi = 0; bi < 4; ++bi) {
                acch[bi] += dh_s[bl+bi][k] * wh;
                accs[bi] += st_s[bl+bi][k] * ws;
            }
        }
    }
    #pragma unroll
    for (int bi = 0; bi < 4; ++bi) {
        const int b = b0 + bl + bi, a = a0 + al;
        const float h = acch[bi] + bh[a];
        g_hidden[(size_t)b*AA + a] = h + bv[a];
        g_sh[(size_t)b*AA + a]     = accs[bi] + bs[a] + h;
    }
}

// ---------------------------------------------------------------------------
// K2: z[m] = bav + sum_a Wav[a]*tanh( enc[m,:]@Wv[:,a] + hidden[b(m),a] )
// fp16 m16n8k16 single pass. BM=128, BN=256 (nt=2), BK=64 (8 stages/nt);
// 512 thr / 16 warps (4m x 4n), warp 32x64. Double-buffered smem + cp.async.
// (UNCHANGED — frozen at the HMMA throughput floor.)
// ---------------------------------------------------------------------------
#define ASTR 20              // uint2 per A row (16 used + 4 pad)
#define BSTR 20              // uint2 per B row (16 used + 4 pad)
#define BUFSZ   61440
#define OFF_H0  122880
#define OFF_H1  123904
#define OFF_WAV 124928
#define OFF_ZS  125952
#define K2_SMEM 126464

__global__ void __launch_bounds__(512, 1) k_zgemm(
    const float* __restrict__ enc, const float* __restrict__ Wav,
    const float* __restrict__ bav)
{
    extern __shared__ unsigned char sm[];
    float* h0s  = (float*)(sm + OFF_H0);
    float* h1s  = (float*)(sm + OFF_H1);
    float* wavs = (float*)(sm + OFF_WAV);
    float* zs   = (float*)(sm + OFF_ZS);
    const uint32_t sbase = (uint32_t)__cvta_generic_to_shared(sm);

    const int tid  = threadIdx.x, lane = tid & 31, wid = tid >> 5;
    const int wm   = wid & 3;
    const int wn   = wid >> 2;
    const int gid  = lane >> 2, tig = lane & 3;
    const int m0   = blockIdx.x * 128;
    const int b0   = m0 / PP;
    const int b1   = (m0 + 127) / PP;
    const int bsplit = (b0 + 1) * PP;

    int sr_[4], sq_[4], skl_[4];
    #pragma unroll
    for (int j = 0; j < 4; ++j) {
        const int slot = tid + j*512;
        sr_[j]  = slot >> 4;
        sq_[j]  = slot & 15;
        skl_[j] = ((sq_[j] >> 2) << 4) + ((sq_[j] & 3) << 1);
    }
    int bn_[4], bs8_[4];
    #pragma unroll
    for (int j = 0; j < 4; ++j) {
        const int i = tid + j*512;
        bn_[j]  = i >> 3;
        bs8_[j] = i & 7;
    }

    if (tid < 128) zs[tid] = 0.f;

    for (int nt = 0; nt < 2; ++nt) {
        const int n0 = nt * 256;
        __syncthreads();
        for (int i = tid; i < 256; i += 512) {
            wavs[i] = Wav[n0 + i];
            h0s[i]  = g_hidden[(size_t)b0*AA + n0 + i];
            h1s[i]  = g_hidden[(size_t)b1*AA + n0 + i];
        }

        float acc[2][8][4];
        #pragma unroll
        for (int mi = 0; mi < 2; ++mi)
            #pragma unroll
            for (int ni = 0; ni < 8; ++ni)
                #pragma unroll
                for (int q = 0; q < 4; ++q) acc[mi][ni][q] = 0.f;

        {
            #pragma unroll
            for (int j = 0; j < 4; ++j) {
                const uint32_t dst = sbase + 20480u + bn_[j]*160u + bs8_[j]*16u;
                cpasync16(dst, &g_WvH4[(size_t)(n0 + bn_[j])*64 + bs8_[j]]);
            }
            CP_COMMIT();
            float2 pa[4][2];
            #pragma unroll
            for (int j = 0; j < 4; ++j) {
                const float* base = &enc[(size_t)(m0 + sr_[j])*DD + skl_[j]];
                pa[j][0] = *(const float2*)(base);
                pa[j][1] = *(const float2*)(base + 8);
            }
            uint2* Ah = (uint2*)(sm);
            #pragma unroll
            for (int j = 0; j < 4; ++j) {
                const int u = sr_[j]*ASTR + sq_[j];
                Ah[u] = make_uint2(pack2h(pa[j][0].x, pa[j][0].y),
                                   pack2h(pa[j][1].x, pa[j][1].y));
            }
            CP_WAIT0();
        }
        __syncthreads();

        int cur = 0;
        for (int kb = 0; kb < DD; kb += 64) {
            const int has_next = (kb + 64 < DD);
            const int nxt = cur ^ 1;
            float2 pa[4][2];
            if (has_next) {
                const int kc = ((kb + 64) >> 4) * 2;
                #pragma unroll
                for (int j = 0; j < 4; ++j) {
                    const uint32_t dst = sbase + (uint32_t)nxt*BUFSZ +
                        20480u + bn_[j]*160u + bs8_[j]*16u;
                    cpasync16(dst, &g_WvH4[(size_t)(n0 + bn_[j])*64 + kc + bs8_[j]]);
                }
                CP_COMMIT();
                #pragma unroll
                for (int j = 0; j < 4; ++j) {
                    const float* base =
                        &enc[(size_t)(m0 + sr_[j])*DD + kb + 64 + skl_[j]];
                    pa[j][0] = *(const float2*)(base);
                    pa[j][1] = *(const float2*)(base + 8);
                }
            }

            {
                uint2* Ah = (uint2*)(sm + cur*BUFSZ);
                uint2* Bh = (uint2*)(sm + cur*BUFSZ + 20480);
                #pragma unroll
                for (int c = 0; c < 4; ++c) {
                    uint32_t ah[2][4];
                    #pragma unroll
                    for (int mi = 0; mi < 2; ++mi) {
                        const int r = wm*32 + mi*16 + gid;
                        const uint2 u0 = Ah[(r    )*ASTR + c*4 + tig];
                        const uint2 u1 = Ah[(r + 8)*ASTR + c*4 + tig];
                        ah[mi][0] = u0.x; ah[mi][1] = u1.x;
                        ah[mi][2] = u0.y; ah[mi][3] = u1.y;
                    }
                    #pragma unroll
                    for (int ni = 0; ni < 8; ++ni) {
                        const int n = wn*64 + ni*8 + gid;
                        const uint2 ubh = Bh[n*BSTR + c*4 + tig];
                        const uint32_t bhf[2] = {ubh.x, ubh.y};
                        #pragma unroll
                        for (int mi = 0; mi < 2; ++mi)
                            mma16h(acc[mi][ni], ah[mi], bhf);
                    }
                }
            }

            if (has_next) {
                uint2* Ah = (uint2*)(sm + nxt*BUFSZ);
                #pragma unroll
                for (int j = 0; j < 4; ++j) {
                    const int u = sr_[j]*ASTR + sq_[j];
                    Ah[u] = make_uint2(pack2h(pa[j][0].x, pa[j][0].y),
                                       pack2h(pa[j][1].x, pa[j][1].y));
                }
                CP_WAIT0();
            }
            __syncthreads();
            cur = nxt;
        }

        float rs[2][2] = {0.f, 0.f, 0.f, 0.f};
        #pragma unroll
        for (int mi = 0; mi < 2; ++mi) {
            const int r_lo = m0 + wm*32 + mi*16 + gid;
            const float* hlo = (r_lo     >= bsplit) ? h1s : h0s;
            const float* hhi = (r_lo + 8 >= bsplit) ? h1s : h0s;
            #pragma unroll
            for (int ni = 0; ni < 8; ++ni) {
                const int c0 = wn*64 + ni*8 + 2*tig;
                const float w0 = wavs[c0], w1 = wavs[c0+1];
                rs[mi][0] += tanhapx(acc[mi][ni][0] + hlo[c0  ]) * w0
                           + tanhapx(acc[mi][ni][1] + hlo[c0+1]) * w1;
                rs[mi][1] += tanhapx(acc[mi][ni][2] + hhi[c0  ]) * w0
                           + tanhapx(acc[mi][ni][3] + hhi[c0+1]) * w1;
            }
        }
        #pragma unroll
        for (int off = 1; off <= 2; off <<= 1) {
            #pragma unroll
            for (int mi = 0; mi < 2; ++mi) {
                rs[mi][0] += __shfl_xor_sync(0xffffffffu, rs[mi][0], off);
                rs[mi][1] += __shfl_xor_sync(0xffffffffu, rs[mi][1], off);
            }
        }
        if (tig == 0) {
            #pragma unroll
            for (int mi = 0; mi < 2; ++mi) {
                atomicAdd(&zs[wm*32 + mi*16 + gid    ], rs[mi][0]);
                atomicAdd(&zs[wm*32 + mi*16 + gid + 8], rs[mi][1]);
            }
        }
    }
    __syncthreads();
    if (tid < 128) g_z[m0 + tid] = zs[tid] + bav[0];
}

// ---------------------------------------------------------------------------
// K3 fused: per-block s_att + softmax + beta (redundant across y), then
// c_t streaming + gated output. grid (B, 4), 256 thr.
// ---------------------------------------------------------------------------
__global__ void __launch_bounds__(256) k_ct(
    const float* __restrict__ enc, const float* __restrict__ st,
    const float* __restrict__ Was, const float* __restrict__ bas,
    float* __restrict__ out)
{
    __shared__ float zsh[PP];
    __shared__ float alpha_sh[PP];
    __shared__ float red[256];
    __shared__ float4 red4[8][32];
    const int tid = threadIdx.x;
    const int b   = blockIdx.x;
    const int y   = blockIdx.y;

    // s_att
    float sacc = 0.f;
    for (int i = tid; i < AA; i += 256)
        sacc += tanhapx(g_sh[(size_t)b*AA + i]) * Was[i];
    red[tid] = sacc;
    __syncthreads();
    for (int s = 128; s > 0; s >>= 1) {
        if (tid < s) red[tid] += red[tid + s];
        __syncthreads();
    }
    const float sa = red[0] + bas[0];
    __syncthreads();

    if (tid < PP) zsh[tid] = g_z[b*PP + tid];
    __syncthreads();

    red[tid] = (tid < PP) ? zsh[tid] : -1e30f;
    __syncthreads();
    for (int s = 128; s > 0; s >>= 1) {
        if (tid < s) red[tid] = fmaxf(red[tid], red[tid + s]);
        __syncthreads();
    }
    const float m1 = red[0];
    __syncthreads();

    const float e = (tid < PP) ? __expf(zsh[tid] - m1) : 0.f;
    red[tid] = e;
    __syncthreads();
    for (int s = 128; s > 0; s >>= 1) {
        if (tid < s) red[tid] += red[tid + s];
        __syncthreads();
    }
    const float sum1 = red[0];

    if (tid < PP) {
        const float alpha = e / sum1;
        alpha_sh[tid] = alpha;
        if (y == 0) out[BB*DD + b*PP + tid] = alpha;     // alpha_t
    }

    const float m2   = fmaxf(m1, sa);
    const float sum2 = sum1 * __expf(m1 - m2) + __expf(sa - m2);
    const float beta = __expf(sa - m2) / sum2;
    if (y == 0 && tid == 0) out[BB*DD + BB*PP + b] = beta;  // beta_t
    __syncthreads();

    // c_t: 32 d-quads x 8 p-groups; warp = one p-group, float4-coalesced.
    const int q  = tid & 31;
    const int g  = tid >> 5;
    const int d4 = y*128 + q*4;
    const float* eb = enc + (size_t)b*PP*DD + d4;
    float4 a4 = make_float4(0.f, 0.f, 0.f, 0.f);
    #pragma unroll 4
    for (int p = g; p < PP; p += 8) {
        const float4 ev = *(const float4*)(eb + (size_t)p*DD);
        const float al = alpha_sh[p];
        a4.x += ev.x*al; a4.y += ev.y*al; a4.z += ev.z*al; a4.w += ev.w*al;
    }
    red4[g][q] = a4;
    __syncthreads();
    #pragma unroll
    for (int s = 4; s > 0; s >>= 1) {
        if (g < s) {
            float4 o = red4[g + s][q];
            a4.x += o.x; a4.y += o.y; a4.z += o.z; a4.w += o.w;
            red4[g][q] = a4;
        }
        __syncthreads();
    }
    if (g == 0) {
        const float4 s4 = *(const float4*)&st[b*DD + d4];
        float4 o;
        o.x = beta*s4.x + (1.f - beta)*a4.x;
        o.y = beta*s4.y + (1.f - beta)*a4.y;
        o.z = beta*s4.z + (1.f - beta)*a4.z;
        o.w = beta*s4.w + (1.f - beta)*a4.w;
        *(float4*)&out[b*DD + d4] = o;                   // c_hat_t
    }
}

// ---------------------------------------------------------------------------
extern "C" void kernel_launch(void* const* d_in, const int* in_sizes, int n_in,
                              void* d_out, int out_size) {
    const float* enc = (const float*)d_in[0];
    const float* dh  = (const float*)d_in[1];
    const float* st  = (const float*)d_in[2];
    const float* Wv  = (const float*)d_in[3];
    const float* bv  = (const float*)d_in[4];
    const float* Wh  = (const float*)d_in[5];
    const float* bh  = (const float*)d_in[6];
    const float* Ws  = (const float*)d_in[7];
    const float* bs  = (const float*)d_in[8];
    const float* Wav = (const float*)d_in[9];
    const float* bav = (const float*)d_in[10];
    const float* Was = (const float*)d_in[11];
    const float* bas = (const float*)d_in[12];
    float* out = (float*)d_out;

    static int smem_set = 0;
    if (!smem_set) {
        cudaFuncSetAttribute(k_zgemm,
            cudaFuncAttributeMaxDynamicSharedMemorySize, K2_SMEM);
        smem_set = 1;
    }

    k_prepc<<<144, 256>>>(dh, st, Wh, bh, Ws, bs, bv, Wv);
    k_zgemm<<<MM/128, 512, K2_SMEM>>>(enc, Wav, bav);
    k_ct   <<<dim3(BB, 4), 256>>>(enc, st, Was, bas, out);
}